// round 8
// baseline (speedup 1.0000x reference)
#include <cuda_runtime.h>
#include <cuda_bf16.h>
#include <mma.h>
#include <math.h>
#include <stdint.h>

using namespace nvcuda;

#define NROWS 8192   // B*Hs*Ws = 2*64*64
#define CDIM  256
#define HEADS 4
#define HD    64
#define GRIDW 64     // Hs = Ws
#define KST   68     // attn smem row stride (floats)
#define ASTR  48     // gemm staging smem stride (bf16) -> 96B rows, LDSM conflict-free
#define CSTR  68     // gemm epilogue smem stride (fp32)

// staging geometry (bytes)
#define TILE_B   (128 * ASTR * 2)      // 12288 B per tile
#define STAGE_B  (4 * TILE_B)          // 49152 B per stage
#define SMEM_TC  (2 * STAGE_B)         // 98304 B total

// -------- scratch (no allocations allowed) --------
__device__ __align__(256) float g_qkv[NROWS * 768];
__device__ __align__(256) float g_qr[NROWS * CDIM];
__device__ __align__(256) float g_kr[NROWS * CDIM];
__device__ __align__(256) float g_width[NROWS * HEADS];
__device__ __align__(256) float g_sharp[NROWS * HEADS];
__device__ __align__(256) float g_attn[NROWS * CDIM];
__device__ __align__(256) float g_irms[NROWS];
// bf16 split operands
__device__ __align__(256) __nv_bfloat16 g_xh[NROWS * 256];
__device__ __align__(256) __nv_bfloat16 g_xl[NROWS * 256];
__device__ __align__(256) __nv_bfloat16 g_vh[NROWS * 256];
__device__ __align__(256) __nv_bfloat16 g_vl[NROWS * 256];
__device__ __align__(256) __nv_bfloat16 g_mh[NROWS * 256];
__device__ __align__(256) __nv_bfloat16 g_ml[NROWS * 256];
// weights transposed to [N][K] bf16 hi/lo
__device__ __align__(256) __nv_bfloat16 g_wqh[768 * 256];
__device__ __align__(256) __nv_bfloat16 g_wql[768 * 256];
__device__ __align__(256) __nv_bfloat16 g_wgh[256 * 256];
__device__ __align__(256) __nv_bfloat16 g_wgl[256 * 256];
__device__ __align__(256) __nv_bfloat16 g_woh[256 * 256];
__device__ __align__(256) __nv_bfloat16 g_wol[256 * 256];

__device__ __forceinline__ float sigm(float x) { return 1.f / (1.f + expf(-x)); }
__device__ __forceinline__ float silu(float x) { return x / (1.f + expf(-x)); }

__device__ __forceinline__ uint32_t smem_u32(const void* p) {
    uint32_t a;
    asm("{ .reg .u64 t; cvta.to.shared.u64 t, %1; cvt.u32.u64 %0, t; }" : "=r"(a) : "l"(p));
    return a;
}
#define CP_ASYNC16(dst_u32, src_ptr) \
    asm volatile("cp.async.cg.shared.global [%0], [%1], 16;" :: "r"(dst_u32), "l"(src_ptr))
#define CP_COMMIT() asm volatile("cp.async.commit_group;" ::: "memory")
#define CP_WAIT1()  asm volatile("cp.async.wait_group 1;" ::: "memory")
#define CP_WAIT0()  asm volatile("cp.async.wait_group 0;" ::: "memory")

// ============================================================================
// prep 1: per-row — bf16 split of x AND width/sharpness projection.
// warp per row.
// ============================================================================
__global__ __launch_bounds__(256) void prep_x_k(
    const float* __restrict__ x, const float* __restrict__ W,
    const float* __restrict__ bias,
    __nv_bfloat16* __restrict__ xh, __nv_bfloat16* __restrict__ xl,
    float* __restrict__ width, float* __restrict__ sharp)
{
    int row = (blockIdx.x * 256 + threadIdx.x) >> 5;
    int lane = threadIdx.x & 31;
    if (row >= NROWS) return;
    const float* xr = x + (size_t)row * 256;
    float acc[8] = {0, 0, 0, 0, 0, 0, 0, 0};
#pragma unroll
    for (int i = 0; i < 8; i++) {
        int k = lane + 32 * i;
        float v = xr[k];
        __nv_bfloat16 h = __float2bfloat16(v);
        xh[row * 256 + k] = h;
        xl[row * 256 + k] = __float2bfloat16(v - __bfloat162float(h));
#pragma unroll
        for (int j = 0; j < 8; j++) acc[j] += v * W[k * 8 + j];
    }
#pragma unroll
    for (int off = 16; off; off >>= 1)
#pragma unroll
        for (int j = 0; j < 8; j++) acc[j] += __shfl_xor_sync(0xffffffffu, acc[j], off);
    if (lane == 0) {
#pragma unroll
        for (int j = 0; j < 4; j++) {
            float wr = silu(acc[j] + bias[j]);
            width[row * 4 + j] = sigm(wr) * 4.2426406871192851f + 0.5f;
            float sr = silu(acc[4 + j] + bias[4 + j]);
            sharp[row * 4 + j] = sigm(sr) * 9.5f + 0.5f;
        }
    }
}

// ============================================================================
// prep 2: all three weights: W [K,N] fp32 -> Wt [N,K] bf16 hi/lo.
// grid covers 768*256 + 256*256 + 256*256 = 327680 elems (1280 blocks).
// ============================================================================
__global__ __launch_bounds__(256) void prep_w_k(
    const float* __restrict__ Wq, const float* __restrict__ Wg,
    const float* __restrict__ Wo,
    __nv_bfloat16* __restrict__ qh, __nv_bfloat16* __restrict__ ql,
    __nv_bfloat16* __restrict__ gh, __nv_bfloat16* __restrict__ gl,
    __nv_bfloat16* __restrict__ oh, __nv_bfloat16* __restrict__ ol)
{
    int idx = blockIdx.x * 256 + threadIdx.x;
    const float* W;
    __nv_bfloat16 *th, *tl;
    int N, off;
    if (idx < 768 * 256)                 { W = Wq; th = qh; tl = ql; N = 768; off = idx; }
    else if (idx < 768 * 256 + 65536)    { W = Wg; th = gh; tl = gl; N = 256; off = idx - 768 * 256; }
    else                                 { W = Wo; th = oh; tl = ol; N = 256; off = idx - 768 * 256 - 65536; }
    int n = off >> 8, k = off & 255;
    float v = W[(size_t)k * N + n];
    __nv_bfloat16 h = __float2bfloat16(v);
    th[off] = h;
    tl[off] = __float2bfloat16(v - __bfloat162float(h));
}

// ============================================================================
// Tensor-core GEMM via wmma bf16 (fp32 accum), 2-term split
// D = Ah*Bh + Ah*Bl + Al*Bh, cp.async double-buffered (2 stages).
// CTA = 128x128, 8 warps (4x2), warp tile 32x64.
// MODE 0 (qkv): C=silu fp32 (ldc=768); for n>=512 also emit v bf16 split.
// MODE 1 (gate): merged = g*v + (1-g)*attn*irms*won; emit merged bf16 split.
// MODE 2 (out):  C=silu fp32 (ldc=256).
// ============================================================================
template <int MODE>
__global__ __launch_bounds__(256) void tc_gemm(
    const __nv_bfloat16* __restrict__ Ah, const __nv_bfloat16* __restrict__ Al,
    const __nv_bfloat16* __restrict__ Bh, const __nv_bfloat16* __restrict__ Bl,
    float* __restrict__ Cp, int ldc,
    const float* __restrict__ bias, const float* __restrict__ qkv,
    const float* __restrict__ attn, const float* __restrict__ irms,
    const float* __restrict__ won,
    __nv_bfloat16* __restrict__ so_h, __nv_bfloat16* __restrict__ so_l)
{
    extern __shared__ char smem[];
    const uint32_t smem_b = smem_u32(smem);
    const int tid = threadIdx.x, wid = tid >> 5, lane = tid & 31;
    const int n0 = blockIdx.x * 128, m0 = blockIdx.y * 128;
    const int wm = wid & 3, wn = wid >> 2;

    // per-thread staging slice: 8 x 16B
    const int which = tid >> 6;                 // 0..3 : Ah/Al/Bh/Bl
    const int tt = tid & 63;                    // 64 threads per tile, 8 rows each x? ->
    // each of the 64 threads copies 8 chunks: rows tt*2, tt*2+1, cols 0..3
    // mapping: chunk c (0..7): row = tt*2 + (c>>2), c8 = (c&3)*8
    const __nv_bfloat16* gsrc;
    if (which == 0)      gsrc = Ah + (size_t)m0 * 256;
    else if (which == 1) gsrc = Al + (size_t)m0 * 256;
    else if (which == 2) gsrc = Bh + (size_t)n0 * 256;
    else                 gsrc = Bl + (size_t)n0 * 256;

    auto issue_stage = [&](int kc, int s) {
        uint32_t dbase = smem_b + s * STAGE_B + which * TILE_B;
#pragma unroll
        for (int c = 0; c < 8; c++) {
            int row = tt * 2 + (c >> 2);
            int c8 = (c & 3) << 3;
            CP_ASYNC16(dbase + row * (ASTR * 2) + c8 * 2,
                       gsrc + (size_t)row * 256 + kc * 32 + c8);
        }
        CP_COMMIT();
    };

    wmma::fragment<wmma::accumulator, 16, 16, 16, float> acc[2][4];
#pragma unroll
    for (int mi = 0; mi < 2; mi++)
#pragma unroll
        for (int ni = 0; ni < 4; ni++) wmma::fill_fragment(acc[mi][ni], 0.f);

    issue_stage(0, 0);

    for (int kc = 0; kc < 8; kc++) {
        if (kc + 1 < 8) { issue_stage(kc + 1, (kc + 1) & 1); CP_WAIT1(); }
        else            { CP_WAIT0(); }
        __syncthreads();

        const __nv_bfloat16* stg = (const __nv_bfloat16*)(smem + (kc & 1) * STAGE_B);
        const __nv_bfloat16* Ash = stg;
        const __nv_bfloat16* Asl = stg + 128 * ASTR;
        const __nv_bfloat16* Bsh = stg + 2 * 128 * ASTR;
        const __nv_bfloat16* Bsl = stg + 3 * 128 * ASTR;

#pragma unroll
        for (int kk = 0; kk < 32; kk += 16) {
            wmma::fragment<wmma::matrix_b, 16, 16, 16, __nv_bfloat16, wmma::col_major> bh[4], bl[4];
#pragma unroll
            for (int ni = 0; ni < 4; ni++) {
                wmma::load_matrix_sync(bh[ni], &Bsh[(wn * 64 + ni * 16) * ASTR + kk], ASTR);
                wmma::load_matrix_sync(bl[ni], &Bsl[(wn * 64 + ni * 16) * ASTR + kk], ASTR);
            }
#pragma unroll
            for (int mi = 0; mi < 2; mi++) {
                wmma::fragment<wmma::matrix_a, 16, 16, 16, __nv_bfloat16, wmma::row_major> ah, al;
                wmma::load_matrix_sync(ah, &Ash[(wm * 32 + mi * 16) * ASTR + kk], ASTR);
                wmma::load_matrix_sync(al, &Asl[(wm * 32 + mi * 16) * ASTR + kk], ASTR);
#pragma unroll
                for (int ni = 0; ni < 4; ni++) {
                    wmma::mma_sync(acc[mi][ni], ah, bh[ni], acc[mi][ni]);
                    wmma::mma_sync(acc[mi][ni], ah, bl[ni], acc[mi][ni]);
                    wmma::mma_sync(acc[mi][ni], al, bh[ni], acc[mi][ni]);
                }
            }
        }
        __syncthreads();
    }

    // epilogue: frags -> per-warp smem region (aliases staging), fused epilogues
    float* Cs = (float*)smem;
#pragma unroll
    for (int mi = 0; mi < 2; mi++)
#pragma unroll
        for (int ni = 0; ni < 4; ni++)
            wmma::store_matrix_sync(&Cs[wid * 32 * CSTR + mi * 16 * CSTR + ni * 16],
                                    acc[mi][ni], CSTR, wmma::mem_row_major);
    __syncwarp();

    for (int i = lane; i < 32 * 64; i += 32) {
        int r = i >> 6, c = i & 63;
        float v = Cs[wid * 32 * CSTR + r * CSTR + c];
        int m = m0 + wm * 32 + r;
        int n = n0 + wn * 64 + c;
        if (MODE == 0) {
            float s = silu(v);
            Cp[(size_t)m * ldc + n] = s;
            if (n >= 512) {
                int vo = m * 256 + n - 512;
                __nv_bfloat16 h = __float2bfloat16(s);
                so_h[vo] = h;
                so_l[vo] = __float2bfloat16(s - __bfloat162float(h));
            }
        } else if (MODE == 1) {
            float g = sigm(silu(v + bias[n]));
            float vv = qkv[(size_t)m * 768 + 512 + n];
            float o = attn[(size_t)m * 256 + n] * irms[m] * won[n];
            float merged = g * vv + (1.f - g) * o;
            __nv_bfloat16 h = __float2bfloat16(merged);
            so_h[m * 256 + n] = h;
            so_l[m * 256 + n] = __float2bfloat16(merged - __bfloat162float(h));
        } else {
            Cp[(size_t)m * ldc + n] = silu(v);
        }
    }
}

// ============================================================================
// rmsnorm + rope on q and k: warp per (row, head).
// ============================================================================
__global__ __launch_bounds__(256) void normrope_k(
    const float* __restrict__ qkv,
    const float* __restrict__ wq, const float* __restrict__ wk,
    float* __restrict__ qr, float* __restrict__ kr)
{
    int g = (blockIdx.x * 256 + threadIdx.x) >> 5;
    int lane = threadIdx.x & 31;
    if (g >= NROWS * HEADS) return;
    int row = g >> 2, h = g & 3;
    const float* qp = qkv + (size_t)row * 768 + h * 64;
    float q1 = qp[lane], q2 = qp[lane + 32];
    float k1 = qp[256 + lane], k2 = qp[256 + lane + 32];
    float sq = q1 * q1 + q2 * q2;
    float sk = k1 * k1 + k2 * k2;
#pragma unroll
    for (int off = 16; off; off >>= 1) {
        sq += __shfl_xor_sync(0xffffffffu, sq, off);
        sk += __shfl_xor_sync(0xffffffffu, sk, off);
    }
    float qi = rsqrtf(sq * (1.f / 64.f) + 1e-6f);
    float ki = rsqrtf(sk * (1.f / 64.f) + 1e-6f);
    q1 *= qi * wq[lane];
    q2 *= qi * wq[lane + 32];
    k1 *= ki * wk[lane];
    k2 *= ki * wk[lane + 32];
    float freq = expf(-9.210340371976184f * (float)lane * (1.f / 32.f));
    float ang = (float)h * freq;
    float cs = cosf(ang), sn = sinf(ang);
    size_t o = (size_t)row * 256 + h * 64;
    qr[o + lane] = q1 * cs - q2 * sn;
    qr[o + lane + 32] = q1 * sn + q2 * cs;
    kr[o + lane] = k1 * cs - k2 * sn;
    kr[o + lane + 32] = k1 * sn + k2 * cs;
}

// ============================================================================
// Local attention (reg scores, shfl softmax/AV, 2 CTAs/SM).
// ============================================================================
__global__ __launch_bounds__(256, 2) void attn_k(
    const float* __restrict__ qr, const float* __restrict__ kr,
    const float* __restrict__ qkv,  // v = cols [512,768)
    const float* __restrict__ width, const float* __restrict__ sharp,
    float* __restrict__ out)
{
    extern __shared__ float sm[];
    float* ks = sm;
    float* vs = sm + 196 * KST;
    const int tile = blockIdx.x, h = blockIdx.y, b = blockIdx.z;
    const int ty0 = (tile >> 3) << 3;
    const int tx0 = (tile & 7) << 3;
    const int tid = threadIdx.x;

    for (int idx = tid; idx < 196 * 16; idx += 256) {
        int sp = idx >> 4, f = idx & 15;
        int yy = ty0 - 3 + sp / 14;
        int xx = tx0 - 3 + sp % 14;
        float4 kv = make_float4(0.f, 0.f, 0.f, 0.f);
        float4 vv = make_float4(0.f, 0.f, 0.f, 0.f);
        if (yy >= 0 && yy < GRIDW && xx >= 0 && xx < GRIDW) {
            int r = (b * GRIDW + yy) * GRIDW + xx;
            kv = *(const float4*)&kr[(size_t)r * 256 + h * 64 + f * 4];
            vv = *(const float4*)&qkv[(size_t)r * 768 + 512 + h * 64 + f * 4];
        }
        *(float4*)&ks[sp * KST + f * 4] = kv;
        *(float4*)&vs[sp * KST + f * 4] = vv;
    }
    __syncthreads();

    const int p = tid >> 2, sub = tid & 3;
    const int py = p >> 3, px = p & 7;
    const int row = (b * GRIDW + ty0 + py) * GRIDW + tx0 + px;

    const float wd = width[row * 4 + h];
    const float sh = sharp[row * 4 + h];

    float sr[13];
    {
        float q[64];
#pragma unroll
        for (int i = 0; i < 16; i++)
            *(float4*)&q[i * 4] = *(const float4*)&qr[(size_t)row * 256 + h * 64 + i * 4];

#pragma unroll
        for (int j = 0; j < 13; j++) {
            int w = sub + 4 * j;
            if (w < 49) {
                int wy = w / 7, wx = w % 7;
                const float* kp = &ks[((py + wy) * 14 + px + wx) * KST];
                float s0 = 0.f, s1 = 0.f, s2 = 0.f, s3 = 0.f;
#pragma unroll
                for (int i = 0; i < 16; i++) {
                    float4 kv = *(const float4*)&kp[i * 4];
                    s0 += q[i * 4 + 0] * kv.x;
                    s1 += q[i * 4 + 1] * kv.y;
                    s2 += q[i * 4 + 2] * kv.z;
                    s3 += q[i * 4 + 3] * kv.w;
                }
                float s = (s0 + s1) + (s2 + s3);
                float dy = (float)(wy - 3), dx = (float)(wx - 3);
                float rd = sqrtf(dy * dy + dx * dx);
                float soft = sigm((wd - rd) * sh);
                sr[j] = s * 0.125f - (1.f - soft) * 10000.f;
            } else {
                sr[j] = -1e30f;
            }
        }
    }

    float mx = sr[0];
#pragma unroll
    for (int j = 1; j < 13; j++) mx = fmaxf(mx, sr[j]);
    mx = fmaxf(mx, __shfl_xor_sync(0xffffffffu, mx, 1));
    mx = fmaxf(mx, __shfl_xor_sync(0xffffffffu, mx, 2));
    float sum = 0.f;
#pragma unroll
    for (int j = 0; j < 13; j++) {
        float e = expf(sr[j] - mx);
        sr[j] = e;
        sum += e;
    }
    sum += __shfl_xor_sync(0xffffffffu, sum, 1);
    sum += __shfl_xor_sync(0xffffffffu, sum, 2);
    float inv = 1.f / sum;

    float o[16];
#pragma unroll
    for (int i = 0; i < 16; i++) o[i] = 0.f;
#pragma unroll
    for (int w = 0; w < 49; w++) {
        const int j = w >> 2, owner = w & 3;
        float a = __shfl_sync(0xffffffffu, sr[j], owner, 4);
        const float* vp = &vs[((py + w / 7) * 14 + px + w % 7) * KST + sub * 16];
#pragma unroll
        for (int i = 0; i < 16; i++) o[i] += a * vp[i];
    }
#pragma unroll
    for (int i = 0; i < 4; i++) {
        float4 r = make_float4(o[i * 4] * inv, o[i * 4 + 1] * inv, o[i * 4 + 2] * inv, o[i * 4 + 3] * inv);
        *(float4*)&out[(size_t)row * 256 + h * 64 + sub * 16 + i * 4] = r;
    }
}

// ============================================================================
// inv-RMS per row of attention output.
// ============================================================================
__global__ __launch_bounds__(256) void irms_k(
    const float* __restrict__ attn, float* __restrict__ irms)
{
    int row = (blockIdx.x * 256 + threadIdx.x) >> 5;
    int lane = threadIdx.x & 31;
    if (row >= NROWS) return;
    const float* a = attn + (size_t)row * 256;
    float s = 0.f;
    for (int k = lane; k < 256; k += 32) {
        float v = a[k];
        s += v * v;
    }
#pragma unroll
    for (int off = 16; off; off >>= 1) s += __shfl_xor_sync(0xffffffffu, s, off);
    if (lane == 0) irms[row] = rsqrtf(s * (1.f / 256.f) + 1e-6f);
}

// ============================================================================
extern "C" void kernel_launch(void* const* d_in, const int* in_sizes, int n_in,
                              void* d_out, int out_size)
{
    const float* x      = (const float*)d_in[0];
    const float* W_qkv  = (const float*)d_in[1];
    const float* w_qn   = (const float*)d_in[2];
    const float* w_kn   = (const float*)d_in[3];
    const float* W_wp   = (const float*)d_in[4];
    const float* b_wp   = (const float*)d_in[5];
    const float* w_on   = (const float*)d_in[6];
    const float* W_out  = (const float*)d_in[7];
    const float* W_gate = (const float*)d_in[8];
    const float* b_gate = (const float*)d_in[9];
    float* out = (float*)d_out;

    float *qkv, *qr, *kr, *wd, *sh, *attn, *irms;
    __nv_bfloat16 *xh, *xl, *vh, *vl, *mh, *ml;
    __nv_bfloat16 *wqh, *wql, *wgh, *wgl, *woh, *wol;
    cudaGetSymbolAddress((void**)&qkv, g_qkv);
    cudaGetSymbolAddress((void**)&qr, g_qr);
    cudaGetSymbolAddress((void**)&kr, g_kr);
    cudaGetSymbolAddress((void**)&wd, g_width);
    cudaGetSymbolAddress((void**)&sh, g_sharp);
    cudaGetSymbolAddress((void**)&attn, g_attn);
    cudaGetSymbolAddress((void**)&irms, g_irms);
    cudaGetSymbolAddress((void**)&xh, g_xh);
    cudaGetSymbolAddress((void**)&xl, g_xl);
    cudaGetSymbolAddress((void**)&vh, g_vh);
    cudaGetSymbolAddress((void**)&vl, g_vl);
    cudaGetSymbolAddress((void**)&mh, g_mh);
    cudaGetSymbolAddress((void**)&ml, g_ml);
    cudaGetSymbolAddress((void**)&wqh, g_wqh);
    cudaGetSymbolAddress((void**)&wql, g_wql);
    cudaGetSymbolAddress((void**)&wgh, g_wgh);
    cudaGetSymbolAddress((void**)&wgl, g_wgl);
    cudaGetSymbolAddress((void**)&woh, g_woh);
    cudaGetSymbolAddress((void**)&wol, g_wol);

    const int SMEM_ATTN = (2 * 196 * KST) * 4;          // 106,624 B -> 2 CTAs/SM
    cudaFuncSetAttribute(attn_k, cudaFuncAttributeMaxDynamicSharedMemorySize, SMEM_ATTN);
    cudaFuncSetAttribute(tc_gemm<0>, cudaFuncAttributeMaxDynamicSharedMemorySize, SMEM_TC);
    cudaFuncSetAttribute(tc_gemm<1>, cudaFuncAttributeMaxDynamicSharedMemorySize, SMEM_TC);
    cudaFuncSetAttribute(tc_gemm<2>, cudaFuncAttributeMaxDynamicSharedMemorySize, SMEM_TC);

    // 0) operand prep (2 launches)
    prep_x_k<<<NROWS / 8, 256>>>(x, W_wp, b_wp, xh, xl, wd, sh);
    prep_w_k<<<1280, 256>>>(W_qkv, W_gate, W_out, wqh, wql, wgh, wgl, woh, wol);

    // 1) qkv = silu(x @ W_qkv); also emits v bf16 split
    tc_gemm<0><<<dim3(6, 64), 256, SMEM_TC>>>(xh, xl, wqh, wql, qkv, 768,
                                              nullptr, nullptr, nullptr, nullptr, nullptr,
                                              vh, vl);
    // 2) rmsnorm + rope on q,k
    normrope_k<<<NROWS * HEADS / 8, 256>>>(qkv, w_qn, w_kn, qr, kr);
    // 3) local attention
    attn_k<<<dim3(64, HEADS, 2), 256, SMEM_ATTN>>>(qr, kr, qkv, wd, sh, attn);
    // 4) inv-rms of attention output
    irms_k<<<NROWS / 8, 256>>>(attn, irms);
    // 5) gate GEMM + merge epilogue -> merged bf16 split
    tc_gemm<1><<<dim3(2, 64), 256, SMEM_TC>>>(vh, vl, wgh, wgl, nullptr, 256,
                                              b_gate, qkv, attn, irms, w_on,
                                              mh, ml);
    // 6) out = silu(merged @ W_out)
    tc_gemm<2><<<dim3(2, 64), 256, SMEM_TC>>>(mh, ml, woh, wol, out, 256,
                                              nullptr, nullptr, nullptr, nullptr, nullptr,
                                              nullptr, nullptr);
}

// round 9
// speedup vs baseline: 1.2124x; 1.2124x over previous
#include <cuda_runtime.h>
#include <cuda_fp16.h>
#include <mma.h>
#include <math.h>
#include <stdint.h>

using namespace nvcuda;

#define NROWS 8192   // B*Hs*Ws = 2*64*64
#define CDIM  256
#define HEADS 4
#define HD    64
#define GRIDW 64     // Hs = Ws
#define KST   68     // attn smem row stride (floats)
#define ASTR  48     // gemm staging smem stride (halves) -> 96B rows
#define CSTR  68     // gemm epilogue smem stride (fp32)
#define TILE_H (128 * ASTR)            // halves per staged tile

// -------- scratch (no allocations allowed) --------
__device__ __align__(256) float g_qr[NROWS * CDIM];
__device__ __align__(256) float g_kr[NROWS * CDIM];
__device__ __align__(256) float g_vf[NROWS * CDIM];
__device__ __align__(256) float g_width[NROWS * HEADS];
__device__ __align__(256) float g_sharp[NROWS * HEADS];
__device__ __align__(256) float g_attn[NROWS * CDIM];
__device__ __align__(256) float g_irms[NROWS];
// fp16 split operands (A side: hi+lo; B side: hi only)
__device__ __align__(256) __half g_xh[NROWS * 256];
__device__ __align__(256) __half g_xl[NROWS * 256];
__device__ __align__(256) __half g_vh[NROWS * 256];
__device__ __align__(256) __half g_vl[NROWS * 256];
__device__ __align__(256) __half g_mh[NROWS * 256];
__device__ __align__(256) __half g_ml[NROWS * 256];
// weights transposed to [N][K] fp16
__device__ __align__(256) __half g_wq[768 * 256];
__device__ __align__(256) __half g_wg[256 * 256];
__device__ __align__(256) __half g_wo[256 * 256];

__device__ __forceinline__ float sigm(float x) { return 1.f / (1.f + expf(-x)); }
__device__ __forceinline__ float silu(float x) { return x / (1.f + expf(-x)); }

// ============================================================================
// prep 1: per-row — fp16 split of x AND width/sharpness projection (warp/row)
// ============================================================================
__global__ __launch_bounds__(256) void prep_x_k(
    const float* __restrict__ x, const float* __restrict__ W,
    const float* __restrict__ bias,
    __half* __restrict__ xh, __half* __restrict__ xl,
    float* __restrict__ width, float* __restrict__ sharp)
{
    int row = (blockIdx.x * 256 + threadIdx.x) >> 5;
    int lane = threadIdx.x & 31;
    if (row >= NROWS) return;
    const float* xr = x + (size_t)row * 256;
    float acc[8] = {0, 0, 0, 0, 0, 0, 0, 0};
#pragma unroll
    for (int i = 0; i < 8; i++) {
        int k = lane + 32 * i;
        float v = xr[k];
        __half h = __float2half(v);
        xh[row * 256 + k] = h;
        xl[row * 256 + k] = __float2half(v - __half2float(h));
#pragma unroll
        for (int j = 0; j < 8; j++) acc[j] += v * W[k * 8 + j];
    }
#pragma unroll
    for (int off = 16; off; off >>= 1)
#pragma unroll
        for (int j = 0; j < 8; j++) acc[j] += __shfl_xor_sync(0xffffffffu, acc[j], off);
    if (lane == 0) {
#pragma unroll
        for (int j = 0; j < 4; j++) {
            float wr = silu(acc[j] + bias[j]);
            width[row * 4 + j] = sigm(wr) * 4.2426406871192851f + 0.5f;
            float sr = silu(acc[4 + j] + bias[4 + j]);
            sharp[row * 4 + j] = sigm(sr) * 9.5f + 0.5f;
        }
    }
}

// ============================================================================
// prep 2: weights: W [K,N] fp32 -> Wt [N,K] fp16 (single precision term)
// ============================================================================
__global__ __launch_bounds__(256) void prep_w_k(
    const float* __restrict__ Wq, const float* __restrict__ Wg,
    const float* __restrict__ Wo,
    __half* __restrict__ tq, __half* __restrict__ tg, __half* __restrict__ to_)
{
    int idx = blockIdx.x * 256 + threadIdx.x;
    const float* W;
    __half* t;
    int N, off;
    if (idx < 768 * 256)              { W = Wq; t = tq; N = 768; off = idx; }
    else if (idx < 768 * 256 + 65536) { W = Wg; t = tg; N = 256; off = idx - 768 * 256; }
    else                              { W = Wo; t = to_; N = 256; off = idx - 768 * 256 - 65536; }
    int n = off >> 8, k = off & 255;
    t[off] = __float2half(W[(size_t)k * N + n]);
}

// ============================================================================
// Tensor-core GEMM via wmma fp16 (fp32 accum), 2-term split:
//   D = Ah*Bh + Al*Bh    (A = Ah+Al in fp16 pair, B single fp16)
// CTA = 128x128, 8 warps (4x2), warp tile 32x64.
// MODE 0 (qkv GEMM): fused epilogue:
//   q,k slices: silu -> rmsnorm (per row,head) -> rope -> write qr/kr
//   v slice:    silu -> write vf fp32 + fp16 split vh/vl
// MODE 1 (gate): g=sigm(silu(acc+bias[n])); merged=g*vf+(1-g)*attn*irms*won;
//                write merged fp16 split mh/ml.
// MODE 2 (out):  C=silu(acc) fp32 (ldc=256).
// ============================================================================
template <int MODE>
__global__ __launch_bounds__(256) void tc_gemm(
    const __half* __restrict__ Ah, const __half* __restrict__ Al,
    const __half* __restrict__ Bh,
    float* __restrict__ Cp, int ldc,
    const float* __restrict__ bias, const float* __restrict__ attn,
    const float* __restrict__ irms, const float* __restrict__ won,
    const float* __restrict__ wqn, const float* __restrict__ wkn,
    float* __restrict__ qr, float* __restrict__ kr, float* __restrict__ vf,
    __half* __restrict__ so_h, __half* __restrict__ so_l)
{
    extern __shared__ char smem[];
    const int tid = threadIdx.x, wid = tid >> 5, lane = tid & 31;
    const int n0 = blockIdx.x * 128, m0 = blockIdx.y * 128;
    const int wm = wid & 3, wn = wid >> 2;

    __half* stg = (__half*)smem;   // 3 tiles x 128 x ASTR halves

    wmma::fragment<wmma::accumulator, 16, 16, 16, float> acc[2][4];
#pragma unroll
    for (int mi = 0; mi < 2; mi++)
#pragma unroll
        for (int ni = 0; ni < 4; ni++) wmma::fill_fragment(acc[mi][ni], 0.f);

    for (int kc = 0; kc < 8; kc++) {
        // stage Ah / Al / Bh tiles: 128 rows x 32 halves each
#pragma unroll
        for (int it = 0; it < 6; it++) {
            int idx = tid + it * 256;
            int which = idx >> 9, t = idx & 511;
            int row = t >> 2, c8 = (t & 3) << 3;
            const __half* gp;
            if (which == 0)      gp = Ah + (size_t)(m0 + row) * 256 + kc * 32 + c8;
            else if (which == 1) gp = Al + (size_t)(m0 + row) * 256 + kc * 32 + c8;
            else                 gp = Bh + (size_t)(n0 + row) * 256 + kc * 32 + c8;
            *(uint4*)&stg[which * TILE_H + row * ASTR + c8] = *(const uint4*)gp;
        }
        __syncthreads();

        const __half* Ash = stg;
        const __half* Asl = stg + TILE_H;
        const __half* Bsh = stg + 2 * TILE_H;

#pragma unroll
        for (int kk = 0; kk < 32; kk += 16) {
            wmma::fragment<wmma::matrix_b, 16, 16, 16, __half, wmma::col_major> bh[4];
#pragma unroll
            for (int ni = 0; ni < 4; ni++)
                wmma::load_matrix_sync(bh[ni], &Bsh[(wn * 64 + ni * 16) * ASTR + kk], ASTR);
#pragma unroll
            for (int mi = 0; mi < 2; mi++) {
                wmma::fragment<wmma::matrix_a, 16, 16, 16, __half, wmma::row_major> ah, al;
                wmma::load_matrix_sync(ah, &Ash[(wm * 32 + mi * 16) * ASTR + kk], ASTR);
                wmma::load_matrix_sync(al, &Asl[(wm * 32 + mi * 16) * ASTR + kk], ASTR);
#pragma unroll
                for (int ni = 0; ni < 4; ni++) {
                    wmma::mma_sync(acc[mi][ni], ah, bh[ni], acc[mi][ni]);
                    wmma::mma_sync(acc[mi][ni], al, bh[ni], acc[mi][ni]);
                }
            }
        }
        __syncthreads();
    }

    // ---- epilogue: frags -> per-warp smem (aliases staging) ----
    float* Cs = (float*)smem;
    float* Cw = Cs + wid * 32 * CSTR;
#pragma unroll
    for (int mi = 0; mi < 2; mi++)
#pragma unroll
        for (int ni = 0; ni < 4; ni++)
            wmma::store_matrix_sync(&Cw[mi * 16 * CSTR + ni * 16],
                                    acc[mi][ni], CSTR, wmma::mem_row_major);
    __syncwarp();

    const int nb2 = n0 + wn * 64;   // this warp's 64-col slice base

    if (MODE == 0) {
        if (nb2 < 512) {
            // q or k head slice: silu -> rmsnorm -> rope, in place (lane = row)
            const bool isq = (nb2 < 256);
            const int h = (isq ? nb2 : nb2 - 256) >> 6;
            const float* wn_ = isq ? wqn : wkn;
            {
                float ss = 0.f;
                float* rp = Cw + lane * CSTR;
#pragma unroll
                for (int c = 0; c < 64; c++) {
                    float v = silu(rp[c]);
                    ss += v * v;
                }
                float rinv = rsqrtf(ss * (1.f / 64.f) + 1e-6f);
#pragma unroll
                for (int c = 0; c < 32; c++) {
                    float q1 = silu(rp[c]) * rinv * wn_[c];
                    float q2 = silu(rp[c + 32]) * rinv * wn_[c + 32];
                    float freq = expf(-9.210340371976184f * (float)c * (1.f / 32.f));
                    float ang = (float)h * freq;
                    float cs = cosf(ang), sn = sinf(ang);
                    rp[c] = q1 * cs - q2 * sn;
                    rp[c + 32] = q1 * sn + q2 * cs;
                }
            }
            __syncwarp();
            float* dst = isq ? qr : kr;
            for (int i = lane; i < 2048; i += 32) {
                int r = i >> 6, c = i & 63;
                int m = m0 + wm * 32 + r;
                dst[m * 256 + h * 64 + c] = Cw[r * CSTR + c];
            }
        } else {
            // v slice: silu -> vf fp32 + fp16 split
            for (int i = lane; i < 2048; i += 32) {
                int r = i >> 6, c = i & 63;
                int m = m0 + wm * 32 + r;
                int n = nb2 - 512 + c;
                float s = silu(Cw[r * CSTR + c]);
                vf[m * 256 + n] = s;
                __half hh = __float2half(s);
                so_h[m * 256 + n] = hh;
                so_l[m * 256 + n] = __float2half(s - __half2float(hh));
            }
        }
    } else if (MODE == 1) {
        for (int i = lane; i < 2048; i += 32) {
            int r = i >> 6, c = i & 63;
            int m = m0 + wm * 32 + r;
            int n = nb2 + c;
            float v = Cw[r * CSTR + c];
            float g = sigm(silu(v + bias[n]));
            float vv = vf[(size_t)m * 256 + n];
            float o = attn[(size_t)m * 256 + n] * irms[m] * won[n];
            float merged = g * vv + (1.f - g) * o;
            __half hh = __float2half(merged);
            so_h[m * 256 + n] = hh;
            so_l[m * 256 + n] = __float2half(merged - __half2float(hh));
        }
    } else {
        for (int i = lane; i < 2048; i += 32) {
            int r = i >> 6, c = i & 63;
            int m = m0 + wm * 32 + r;
            int n = nb2 + c;
            Cp[(size_t)m * ldc + n] = silu(Cw[r * CSTR + c]);
        }
    }
}

// ============================================================================
// Local attention (reg scores, shfl softmax/AV, 2 CTAs/SM).
// ============================================================================
__global__ __launch_bounds__(256, 2) void attn_k(
    const float* __restrict__ qr, const float* __restrict__ kr,
    const float* __restrict__ vfp,
    const float* __restrict__ width, const float* __restrict__ sharp,
    float* __restrict__ out)
{
    extern __shared__ float sm[];
    float* ks = sm;
    float* vs = sm + 196 * KST;
    const int tile = blockIdx.x, h = blockIdx.y, b = blockIdx.z;
    const int ty0 = (tile >> 3) << 3;
    const int tx0 = (tile & 7) << 3;
    const int tid = threadIdx.x;

    for (int idx = tid; idx < 196 * 16; idx += 256) {
        int sp = idx >> 4, f = idx & 15;
        int yy = ty0 - 3 + sp / 14;
        int xx = tx0 - 3 + sp % 14;
        float4 kv = make_float4(0.f, 0.f, 0.f, 0.f);
        float4 vv = make_float4(0.f, 0.f, 0.f, 0.f);
        if (yy >= 0 && yy < GRIDW && xx >= 0 && xx < GRIDW) {
            int r = (b * GRIDW + yy) * GRIDW + xx;
            kv = *(const float4*)&kr[(size_t)r * 256 + h * 64 + f * 4];
            vv = *(const float4*)&vfp[(size_t)r * 256 + h * 64 + f * 4];
        }
        *(float4*)&ks[sp * KST + f * 4] = kv;
        *(float4*)&vs[sp * KST + f * 4] = vv;
    }
    __syncthreads();

    const int p = tid >> 2, sub = tid & 3;
    const int py = p >> 3, px = p & 7;
    const int row = (b * GRIDW + ty0 + py) * GRIDW + tx0 + px;

    const float wd = width[row * 4 + h];
    const float sh = sharp[row * 4 + h];

    float sr[13];
    {
        float q[64];
#pragma unroll
        for (int i = 0; i < 16; i++)
            *(float4*)&q[i * 4] = *(const float4*)&qr[(size_t)row * 256 + h * 64 + i * 4];

#pragma unroll
        for (int j = 0; j < 13; j++) {
            int w = sub + 4 * j;
            if (w < 49) {
                int wy = w / 7, wx = w % 7;
                const float* kp = &ks[((py + wy) * 14 + px + wx) * KST];
                float s0 = 0.f, s1 = 0.f, s2 = 0.f, s3 = 0.f;
#pragma unroll
                for (int i = 0; i < 16; i++) {
                    float4 kv = *(const float4*)&kp[i * 4];
                    s0 += q[i * 4 + 0] * kv.x;
                    s1 += q[i * 4 + 1] * kv.y;
                    s2 += q[i * 4 + 2] * kv.z;
                    s3 += q[i * 4 + 3] * kv.w;
                }
                float s = (s0 + s1) + (s2 + s3);
                float dy = (float)(wy - 3), dx = (float)(wx - 3);
                float rd = sqrtf(dy * dy + dx * dx);
                float soft = sigm((wd - rd) * sh);
                sr[j] = s * 0.125f - (1.f - soft) * 10000.f;
            } else {
                sr[j] = -1e30f;
            }
        }
    }

    float mx = sr[0];
#pragma unroll
    for (int j = 1; j < 13; j++) mx = fmaxf(mx, sr[j]);
    mx = fmaxf(mx, __shfl_xor_sync(0xffffffffu, mx, 1));
    mx = fmaxf(mx, __shfl_xor_sync(0xffffffffu, mx, 2));
    float sum = 0.f;
#pragma unroll
    for (int j = 0; j < 13; j++) {
        float e = expf(sr[j] - mx);
        sr[j] = e;
        sum += e;
    }
    sum += __shfl_xor_sync(0xffffffffu, sum, 1);
    sum += __shfl_xor_sync(0xffffffffu, sum, 2);
    float inv = 1.f / sum;

    float o[16];
#pragma unroll
    for (int i = 0; i < 16; i++) o[i] = 0.f;
#pragma unroll
    for (int w = 0; w < 49; w++) {
        const int j = w >> 2, owner = w & 3;
        float a = __shfl_sync(0xffffffffu, sr[j], owner, 4);
        const float* vp = &vs[((py + w / 7) * 14 + px + w % 7) * KST + sub * 16];
#pragma unroll
        for (int i = 0; i < 16; i++) o[i] += a * vp[i];
    }
#pragma unroll
    for (int i = 0; i < 4; i++) {
        float4 r = make_float4(o[i * 4] * inv, o[i * 4 + 1] * inv, o[i * 4 + 2] * inv, o[i * 4 + 3] * inv);
        *(float4*)&out[(size_t)row * 256 + h * 64 + sub * 16 + i * 4] = r;
    }
}

// ============================================================================
// inv-RMS per row of attention output.
// ============================================================================
__global__ __launch_bounds__(256) void irms_k(
    const float* __restrict__ attn, float* __restrict__ irms)
{
    int row = (blockIdx.x * 256 + threadIdx.x) >> 5;
    int lane = threadIdx.x & 31;
    if (row >= NROWS) return;
    const float* a = attn + (size_t)row * 256;
    float s = 0.f;
    for (int k = lane; k < 256; k += 32) {
        float v = a[k];
        s += v * v;
    }
#pragma unroll
    for (int off = 16; off; off >>= 1) s += __shfl_xor_sync(0xffffffffu, s, off);
    if (lane == 0) irms[row] = rsqrtf(s * (1.f / 256.f) + 1e-6f);
}

// ============================================================================
extern "C" void kernel_launch(void* const* d_in, const int* in_sizes, int n_in,
                              void* d_out, int out_size)
{
    const float* x      = (const float*)d_in[0];
    const float* W_qkv  = (const float*)d_in[1];
    const float* w_qn   = (const float*)d_in[2];
    const float* w_kn   = (const float*)d_in[3];
    const float* W_wp   = (const float*)d_in[4];
    const float* b_wp   = (const float*)d_in[5];
    const float* w_on   = (const float*)d_in[6];
    const float* W_out  = (const float*)d_in[7];
    const float* W_gate = (const float*)d_in[8];
    const float* b_gate = (const float*)d_in[9];
    float* out = (float*)d_out;

    float *qr, *kr, *vf, *wd, *sh, *attn, *irms;
    __half *xh, *xl, *vh, *vl, *mh, *ml, *wq, *wg, *wo;
    cudaGetSymbolAddress((void**)&qr, g_qr);
    cudaGetSymbolAddress((void**)&kr, g_kr);
    cudaGetSymbolAddress((void**)&vf, g_vf);
    cudaGetSymbolAddress((void**)&wd, g_width);
    cudaGetSymbolAddress((void**)&sh, g_sharp);
    cudaGetSymbolAddress((void**)&attn, g_attn);
    cudaGetSymbolAddress((void**)&irms, g_irms);
    cudaGetSymbolAddress((void**)&xh, g_xh);
    cudaGetSymbolAddress((void**)&xl, g_xl);
    cudaGetSymbolAddress((void**)&vh, g_vh);
    cudaGetSymbolAddress((void**)&vl, g_vl);
    cudaGetSymbolAddress((void**)&mh, g_mh);
    cudaGetSymbolAddress((void**)&ml, g_ml);
    cudaGetSymbolAddress((void**)&wq, g_wq);
    cudaGetSymbolAddress((void**)&wg, g_wg);
    cudaGetSymbolAddress((void**)&wo, g_wo);

    const int SMEM_ATTN = (2 * 196 * KST) * 4;   // 106,624 B -> 2 CTAs/SM
    cudaFuncSetAttribute(attn_k, cudaFuncAttributeMaxDynamicSharedMemorySize, SMEM_ATTN);
    const int SMEM_TC = 8 * 32 * CSTR * 4;       // 69,632 B (staging 36,864 aliased)
    cudaFuncSetAttribute(tc_gemm<0>, cudaFuncAttributeMaxDynamicSharedMemorySize, SMEM_TC);
    cudaFuncSetAttribute(tc_gemm<1>, cudaFuncAttributeMaxDynamicSharedMemorySize, SMEM_TC);
    cudaFuncSetAttribute(tc_gemm<2>, cudaFuncAttributeMaxDynamicSharedMemorySize, SMEM_TC);

    // 0) operand prep
    prep_x_k<<<NROWS / 8, 256>>>(x, W_wp, b_wp, xh, xl, wd, sh);
    prep_w_k<<<1280, 256>>>(W_qkv, W_gate, W_out, wq, wg, wo);

    // 1) qkv GEMM + fused silu/rmsnorm/rope epilogue -> qr, kr, vf (+ v splits)
    tc_gemm<0><<<dim3(6, 64), 256, SMEM_TC>>>(xh, xl, wq, nullptr, 0,
                                              nullptr, nullptr, nullptr, nullptr,
                                              w_qn, w_kn, qr, kr, vf, vh, vl);
    // 2) local attention
    attn_k<<<dim3(64, HEADS, 2), 256, SMEM_ATTN>>>(qr, kr, vf, wd, sh, attn);
    // 3) inv-rms of attention output
    irms_k<<<NROWS / 8, 256>>>(attn, irms);
    // 4) gate GEMM + merge epilogue -> merged fp16 split
    tc_gemm<1><<<dim3(2, 64), 256, SMEM_TC>>>(vh, vl, wg, nullptr, 0,
                                              b_gate, attn, irms, w_on,
                                              nullptr, nullptr, nullptr, nullptr, vf,
                                              mh, ml);
    // 5) out = silu(merged @ W_out)
    tc_gemm<2><<<dim3(2, 64), 256, SMEM_TC>>>(mh, ml, wo, out, 256,
                                              nullptr, nullptr, nullptr, nullptr,
                                              nullptr, nullptr, nullptr, nullptr, nullptr,
                                              nullptr, nullptr);
}

// round 10
// speedup vs baseline: 1.3731x; 1.1326x over previous
#include <cuda_runtime.h>
#include <cuda_fp16.h>
#include <mma.h>
#include <math.h>
#include <stdint.h>

using namespace nvcuda;

#define NROWS 8192   // B*Hs*Ws = 2*64*64
#define CDIM  256
#define HEADS 4
#define HD    64
#define GRIDW 64     // Hs = Ws
#define ASTR  48     // gemm staging smem stride (halves) -> 96B rows
#define CSTR  68     // gemm epilogue smem stride (fp32)
#define TILE_H (128 * ASTR)

// attn smem layout (bytes)
#define VH_B   0          // Vh fp16 [208][72]
#define KH_B   29952      // Kh fp16 [208][72]   (inside S region, freed before S store)
#define QH_B   59904      // Qh fp16 [64][72]
#define QL_B   69120      // Ql fp16 [64][72]
#define S_B    29952      // S fp32 [64][216]  (A fp16 split in-place; O fp32 after)
#define SMEM_AT 85248

// -------- scratch (no allocations allowed) --------
__device__ __align__(256) float g_vf[NROWS * CDIM];
__device__ __align__(256) float g_width[NROWS * HEADS];
__device__ __align__(256) float g_sharp[NROWS * HEADS];
__device__ __align__(256) float g_attn[NROWS * CDIM];
__device__ __align__(256) float g_irms[NROWS];
// fp16 operands
__device__ __align__(256) __half g_xh[NROWS * 256];
__device__ __align__(256) __half g_xl[NROWS * 256];
__device__ __align__(256) __half g_qh[NROWS * 256];
__device__ __align__(256) __half g_ql[NROWS * 256];
__device__ __align__(256) __half g_kh[NROWS * 256];
__device__ __align__(256) __half g_vh[NROWS * 256];
__device__ __align__(256) __half g_vl[NROWS * 256];
__device__ __align__(256) __half g_mh[NROWS * 256];
__device__ __align__(256) __half g_ml[NROWS * 256];
// weights transposed to [N][K] fp16
__device__ __align__(256) __half g_wq[768 * 256];
__device__ __align__(256) __half g_wg[256 * 256];
__device__ __align__(256) __half g_wo[256 * 256];

__device__ __forceinline__ float sigm(float x) { return 1.f / (1.f + expf(-x)); }
__device__ __forceinline__ float silu(float x) { return x / (1.f + expf(-x)); }

// ============================================================================
// prep 1: per-row — fp16 split of x AND width/sharpness projection (warp/row)
// ============================================================================
__global__ __launch_bounds__(256) void prep_x_k(
    const float* __restrict__ x, const float* __restrict__ W,
    const float* __restrict__ bias,
    __half* __restrict__ xh, __half* __restrict__ xl,
    float* __restrict__ width, float* __restrict__ sharp)
{
    int row = (blockIdx.x * 256 + threadIdx.x) >> 5;
    int lane = threadIdx.x & 31;
    if (row >= NROWS) return;
    const float* xr = x + (size_t)row * 256;
    float acc[8] = {0, 0, 0, 0, 0, 0, 0, 0};
#pragma unroll
    for (int i = 0; i < 8; i++) {
        int k = lane + 32 * i;
        float v = xr[k];
        __half h = __float2half(v);
        xh[row * 256 + k] = h;
        xl[row * 256 + k] = __float2half(v - __half2float(h));
#pragma unroll
        for (int j = 0; j < 8; j++) acc[j] += v * W[k * 8 + j];
    }
#pragma unroll
    for (int off = 16; off; off >>= 1)
#pragma unroll
        for (int j = 0; j < 8; j++) acc[j] += __shfl_xor_sync(0xffffffffu, acc[j], off);
    if (lane == 0) {
#pragma unroll
        for (int j = 0; j < 4; j++) {
            float wr = silu(acc[j] + bias[j]);
            width[row * 4 + j] = sigm(wr) * 4.2426406871192851f + 0.5f;
            float sr = silu(acc[4 + j] + bias[4 + j]);
            sharp[row * 4 + j] = sigm(sr) * 9.5f + 0.5f;
        }
    }
}

// ============================================================================
// prep 2: weights: W [K,N] fp32 -> Wt [N,K] fp16
// ============================================================================
__global__ __launch_bounds__(256) void prep_w_k(
    const float* __restrict__ Wq, const float* __restrict__ Wg,
    const float* __restrict__ Wo,
    __half* __restrict__ tq, __half* __restrict__ tg, __half* __restrict__ to_)
{
    int idx = blockIdx.x * 256 + threadIdx.x;
    const float* W;
    __half* t;
    int N, off;
    if (idx < 768 * 256)              { W = Wq; t = tq; N = 768; off = idx; }
    else if (idx < 768 * 256 + 65536) { W = Wg; t = tg; N = 256; off = idx - 768 * 256; }
    else                              { W = Wo; t = to_; N = 256; off = idx - 768 * 256 - 65536; }
    int n = off >> 8, k = off & 255;
    t[off] = __float2half(W[(size_t)k * N + n]);
}

// ============================================================================
// Tensor-core GEMM (wmma fp16, fp32 accum), 2-term split D = Ah*B + Al*B.
// CTA = 128x128, 8 warps (4x2), warp tile 32x64.
// MODE 0 (qkv): q,k: silu->rmsnorm->rope -> q fp16 split (qh,ql), k fp16 (kh)
//               v: silu -> vf fp32 + fp16 split vh/vl
// MODE 1 (gate): merged = g*vf + (1-g)*attn*irms*won -> fp16 split mh/ml
// MODE 2 (out):  C = silu(acc) fp32
// ============================================================================
template <int MODE>
__global__ __launch_bounds__(256) void tc_gemm(
    const __half* __restrict__ Ah, const __half* __restrict__ Al,
    const __half* __restrict__ Bh,
    float* __restrict__ Cp, int ldc,
    const float* __restrict__ bias, const float* __restrict__ attn,
    const float* __restrict__ irms, const float* __restrict__ won,
    const float* __restrict__ wqn, const float* __restrict__ wkn,
    __half* __restrict__ qh_o, __half* __restrict__ ql_o, __half* __restrict__ kh_o,
    float* __restrict__ vf,
    __half* __restrict__ so_h, __half* __restrict__ so_l)
{
    extern __shared__ char smem[];
    const int tid = threadIdx.x, wid = tid >> 5, lane = tid & 31;
    const int n0 = blockIdx.x * 128, m0 = blockIdx.y * 128;
    const int wm = wid & 3, wn = wid >> 2;

    __half* stg = (__half*)smem;

    wmma::fragment<wmma::accumulator, 16, 16, 16, float> acc[2][4];
#pragma unroll
    for (int mi = 0; mi < 2; mi++)
#pragma unroll
        for (int ni = 0; ni < 4; ni++) wmma::fill_fragment(acc[mi][ni], 0.f);

    for (int kc = 0; kc < 8; kc++) {
#pragma unroll
        for (int it = 0; it < 6; it++) {
            int idx = tid + it * 256;
            int which = idx >> 9, t = idx & 511;
            int row = t >> 2, c8 = (t & 3) << 3;
            const __half* gp;
            if (which == 0)      gp = Ah + (size_t)(m0 + row) * 256 + kc * 32 + c8;
            else if (which == 1) gp = Al + (size_t)(m0 + row) * 256 + kc * 32 + c8;
            else                 gp = Bh + (size_t)(n0 + row) * 256 + kc * 32 + c8;
            *(uint4*)&stg[which * TILE_H + row * ASTR + c8] = *(const uint4*)gp;
        }
        __syncthreads();

        const __half* Ash = stg;
        const __half* Asl = stg + TILE_H;
        const __half* Bsh = stg + 2 * TILE_H;

#pragma unroll
        for (int kk = 0; kk < 32; kk += 16) {
            wmma::fragment<wmma::matrix_b, 16, 16, 16, __half, wmma::col_major> bh[4];
#pragma unroll
            for (int ni = 0; ni < 4; ni++)
                wmma::load_matrix_sync(bh[ni], &Bsh[(wn * 64 + ni * 16) * ASTR + kk], ASTR);
#pragma unroll
            for (int mi = 0; mi < 2; mi++) {
                wmma::fragment<wmma::matrix_a, 16, 16, 16, __half, wmma::row_major> ah, al;
                wmma::load_matrix_sync(ah, &Ash[(wm * 32 + mi * 16) * ASTR + kk], ASTR);
                wmma::load_matrix_sync(al, &Asl[(wm * 32 + mi * 16) * ASTR + kk], ASTR);
#pragma unroll
                for (int ni = 0; ni < 4; ni++) {
                    wmma::mma_sync(acc[mi][ni], ah, bh[ni], acc[mi][ni]);
                    wmma::mma_sync(acc[mi][ni], al, bh[ni], acc[mi][ni]);
                }
            }
        }
        __syncthreads();
    }

    float* Cs = (float*)smem;
    float* Cw = Cs + wid * 32 * CSTR;
#pragma unroll
    for (int mi = 0; mi < 2; mi++)
#pragma unroll
        for (int ni = 0; ni < 4; ni++)
            wmma::store_matrix_sync(&Cw[mi * 16 * CSTR + ni * 16],
                                    acc[mi][ni], CSTR, wmma::mem_row_major);
    __syncwarp();

    const int nb2 = n0 + wn * 64;

    if (MODE == 0) {
        if (nb2 < 512) {
            const bool isq = (nb2 < 256);
            const int h = (isq ? nb2 : nb2 - 256) >> 6;
            const float* wn_ = isq ? wqn : wkn;
            {
                float ss = 0.f;
                float* rp = Cw + lane * CSTR;
#pragma unroll
                for (int c = 0; c < 64; c++) {
                    float v = silu(rp[c]);
                    ss += v * v;
                }
                float rinv = rsqrtf(ss * (1.f / 64.f) + 1e-6f);
#pragma unroll
                for (int c = 0; c < 32; c++) {
                    float q1 = silu(rp[c]) * rinv * wn_[c];
                    float q2 = silu(rp[c + 32]) * rinv * wn_[c + 32];
                    float freq = expf(-9.210340371976184f * (float)c * (1.f / 32.f));
                    float ang = (float)h * freq;
                    float cs = cosf(ang), sn = sinf(ang);
                    rp[c] = q1 * cs - q2 * sn;
                    rp[c + 32] = q1 * sn + q2 * cs;
                }
            }
            __syncwarp();
            for (int i = lane; i < 2048; i += 32) {
                int r = i >> 6, c = i & 63;
                int m = m0 + wm * 32 + r;
                float v = Cw[r * CSTR + c];
                int o = m * 256 + h * 64 + c;
                if (isq) {
                    __half hh = __float2half(v);
                    qh_o[o] = hh;
                    ql_o[o] = __float2half(v - __half2float(hh));
                } else {
                    kh_o[o] = __float2half(v);
                }
            }
        } else {
            for (int i = lane; i < 2048; i += 32) {
                int r = i >> 6, c = i & 63;
                int m = m0 + wm * 32 + r;
                int n = nb2 - 512 + c;
                float s = silu(Cw[r * CSTR + c]);
                vf[m * 256 + n] = s;
                __half hh = __float2half(s);
                so_h[m * 256 + n] = hh;
                so_l[m * 256 + n] = __float2half(s - __half2float(hh));
            }
        }
    } else if (MODE == 1) {
        for (int i = lane; i < 2048; i += 32) {
            int r = i >> 6, c = i & 63;
            int m = m0 + wm * 32 + r;
            int n = nb2 + c;
            float v = Cw[r * CSTR + c];
            float g = sigm(silu(v + bias[n]));
            float vv = vf[(size_t)m * 256 + n];
            float o = attn[(size_t)m * 256 + n] * irms[m] * won[n];
            float merged = g * vv + (1.f - g) * o;
            __half hh = __float2half(merged);
            so_h[m * 256 + n] = hh;
            so_l[m * 256 + n] = __float2half(merged - __half2float(hh));
        }
    } else {
        for (int i = lane; i < 2048; i += 32) {
            int r = i >> 6, c = i & 63;
            int m = m0 + wm * 32 + r;
            int n = nb2 + c;
            Cp[(size_t)m * ldc + n] = silu(Cw[r * CSTR + c]);
        }
    }
}

// ============================================================================
// Local attention via wmma:
//   S[64,208] = (Qh+Ql)[64,64] @ Kh^T    (q fp16 split, k fp16)
//   softmax over each query's 49-window (mask), A = attn weights fp16 split
//   O[64,64]  = (Ah+Al)[64,208] @ Vh[208,64]
// Block = (8x8 tile, head, batch), 256 threads, 2 CTAs/SM.
// ============================================================================
__global__ __launch_bounds__(256, 2) void attn_k(
    const __half* __restrict__ gqh, const __half* __restrict__ gql,
    const __half* __restrict__ gkh, const __half* __restrict__ gvh,
    const float* __restrict__ width, const float* __restrict__ sharp,
    float* __restrict__ out)
{
    extern __shared__ char smem[];
    __half* Vh = (__half*)(smem + VH_B);   // [208][72]
    __half* Kh = (__half*)(smem + KH_B);   // [208][72]
    __half* Qh = (__half*)(smem + QH_B);   // [64][72]
    __half* Ql = (__half*)(smem + QL_B);   // [64][72]
    float*  S  = (float*)(smem + S_B);     // [64][216]

    const int tile = blockIdx.x, h = blockIdx.y, b = blockIdx.z;
    const int ty0 = (tile >> 3) << 3;
    const int tx0 = (tile & 7) << 3;
    const int tid = threadIdx.x, wid = tid >> 5, lane = tid & 31;

    // ---- load: Kh(208) Vh(208) Qh(64) Ql(64) rows x 8 x uint4 ----
    const uint4 zero4 = make_uint4(0, 0, 0, 0);
    for (int idx = tid; idx < 4352; idx += 256) {
        int job = idx >> 3, c = (idx & 7) << 3;
        uint4 val = zero4;
        __half* dst;
        if (job < 416) {
            int isv = job >= 208;
            int sp = isv ? job - 208 : job;
            dst = (isv ? Vh : Kh) + sp * 72 + c;
            if (sp < 196) {
                int yy = ty0 - 3 + sp / 14;
                int xx = tx0 - 3 + sp % 14;
                if (yy >= 0 && yy < GRIDW && xx >= 0 && xx < GRIDW) {
                    int r = (b * GRIDW + yy) * GRIDW + xx;
                    val = *(const uint4*)&(isv ? gvh : gkh)[(size_t)r * 256 + h * 64 + c];
                }
            }
        } else {
            int r0 = job - 416;
            int isl = r0 >= 64;
            int p = r0 & 63;
            dst = (isl ? Ql : Qh) + p * 72 + c;
            int r = (b * GRIDW + ty0 + (p >> 3)) * GRIDW + tx0 + (p & 7);
            val = *(const uint4*)&(isl ? gql : gqh)[(size_t)r * 256 + h * 64 + c];
        }
        *(uint4*)dst = val;
    }
    __syncthreads();

    const int wm = wid & 3, wn = wid >> 2;

    // ---- QK MMA: warp (wm, wn): m-tile wm, n-tiles [wn*7, wn*7+NJ) ----
    {
        const int JN0 = wn * 7, NJ = wn ? 6 : 7;
        wmma::fragment<wmma::accumulator, 16, 16, 16, float> sacc[7];
#pragma unroll
        for (int j = 0; j < 7; j++) wmma::fill_fragment(sacc[j], 0.f);
#pragma unroll
        for (int kt = 0; kt < 4; kt++) {
            wmma::fragment<wmma::matrix_a, 16, 16, 16, __half, wmma::row_major> aqh, aql;
            wmma::load_matrix_sync(aqh, &Qh[wm * 16 * 72 + kt * 16], 72);
            wmma::load_matrix_sync(aql, &Ql[wm * 16 * 72 + kt * 16], 72);
            for (int j = 0; j < NJ; j++) {
                wmma::fragment<wmma::matrix_b, 16, 16, 16, __half, wmma::col_major> bk;
                wmma::load_matrix_sync(bk, &Kh[(JN0 + j) * 16 * 72 + kt * 16], 72);
                wmma::mma_sync(sacc[j], aqh, bk, sacc[j]);
                wmma::mma_sync(sacc[j], aql, bk, sacc[j]);
            }
        }
        __syncthreads();   // all QK smem reads done before S overwrites Kh/Qh/Ql
        for (int j = 0; j < NJ; j++)
            wmma::store_matrix_sync(&S[wm * 16 * 216 + (JN0 + j) * 16], sacc[j], 216,
                                    wmma::mem_row_major);
    }
    __syncthreads();

    // ---- softmax + A split (in-place over S rows) ----
    {
        const int p = tid >> 2, sub = tid & 3;
        const int py = p >> 3, px = p & 7;
        const int row = (b * GRIDW + ty0 + py) * GRIDW + tx0 + px;
        const float wd = width[row * 4 + h];
        const float sh = sharp[row * 4 + h];
        float* srow = S + p * 216;

        float sr[13];
#pragma unroll
        for (int j = 0; j < 13; j++) {
            int w = sub + 4 * j;
            if (w < 49) {
                int wy = w / 7, wx = w % 7;
                float dy = (float)(wy - 3), dx = (float)(wx - 3);
                float rd = sqrtf(dy * dy + dx * dx);
                float soft = sigm((wd - rd) * sh);
                sr[j] = srow[(py + wy) * 14 + px + wx] * 0.125f - (1.f - soft) * 10000.f;
            } else {
                sr[j] = -1e30f;
            }
        }
        float mx = sr[0];
#pragma unroll
        for (int j = 1; j < 13; j++) mx = fmaxf(mx, sr[j]);
        mx = fmaxf(mx, __shfl_xor_sync(0xffffffffu, mx, 1));
        mx = fmaxf(mx, __shfl_xor_sync(0xffffffffu, mx, 2));
        float sum = 0.f;
#pragma unroll
        for (int j = 0; j < 13; j++) {
            float e = expf(sr[j] - mx);
            sr[j] = e;
            sum += e;
        }
        sum += __shfl_xor_sync(0xffffffffu, sum, 1);
        sum += __shfl_xor_sync(0xffffffffu, sum, 2);
        float inv = 1.f / sum;

        __syncwarp();   // all reads of S rows done before overwrite
        // zero-fill this row's A region (216 floats = Ah[216]+Al[216] halves)
        float2* zrow = (float2*)srow;
#pragma unroll
        for (int i = 0; i < 27; i++) zrow[sub * 27 + i] = make_float2(0.f, 0.f);
        __syncwarp();
        __half* ah_row = (__half*)srow;
        __half* al_row = ah_row + 216;
#pragma unroll
        for (int j = 0; j < 13; j++) {
            int w = sub + 4 * j;
            if (w < 49) {
                int hi = (py + w / 7) * 14 + px + w % 7;
                float a = sr[j] * inv;
                __half hh = __float2half(a);
                ah_row[hi] = hh;
                al_row[hi] = __float2half(a - __half2float(hh));
            }
        }
    }
    __syncthreads();

    // ---- AV MMA: warp (wm, wn): rows wm*16, cols wn*32 ----
    {
        const __half* Ah = (const __half*)(smem + S_B);         // lda 432 halves
        const __half* Al = Ah + 216;
        wmma::fragment<wmma::accumulator, 16, 16, 16, float> oacc[2];
        wmma::fill_fragment(oacc[0], 0.f);
        wmma::fill_fragment(oacc[1], 0.f);
        for (int kt = 0; kt < 13; kt++) {
            wmma::fragment<wmma::matrix_a, 16, 16, 16, __half, wmma::row_major> fah, fal;
            wmma::load_matrix_sync(fah, &Ah[wm * 16 * 432 + kt * 16], 432);
            wmma::load_matrix_sync(fal, &Al[wm * 16 * 432 + kt * 16], 432);
#pragma unroll
            for (int ni = 0; ni < 2; ni++) {
                wmma::fragment<wmma::matrix_b, 16, 16, 16, __half, wmma::row_major> bv;
                wmma::load_matrix_sync(bv, &Vh[kt * 16 * 72 + wn * 32 + ni * 16], 72);
                wmma::mma_sync(oacc[ni], fah, bv, oacc[ni]);
                wmma::mma_sync(oacc[ni], fal, bv, oacc[ni]);
            }
        }
        __syncthreads();   // A reads done before O overwrites S region
        float* O = (float*)(smem + S_B);   // [64][72]
#pragma unroll
        for (int ni = 0; ni < 2; ni++)
            wmma::store_matrix_sync(&O[wm * 16 * 72 + wn * 32 + ni * 16], oacc[ni], 72,
                                    wmma::mem_row_major);
    }
    __syncthreads();

    // ---- write out ----
    {
        const float* O = (const float*)(smem + S_B);
        for (int idx = tid; idx < 1024; idx += 256) {
            int p = idx >> 4, d4 = (idx & 15) << 2;
            int r = (b * GRIDW + ty0 + (p >> 3)) * GRIDW + tx0 + (p & 7);
            *(float4*)&out[(size_t)r * 256 + h * 64 + d4] = *(const float4*)&O[p * 72 + d4];
        }
    }
}

// ============================================================================
// inv-RMS per row of attention output.
// ============================================================================
__global__ __launch_bounds__(256) void irms_k(
    const float* __restrict__ attn, float* __restrict__ irms)
{
    int row = (blockIdx.x * 256 + threadIdx.x) >> 5;
    int lane = threadIdx.x & 31;
    if (row >= NROWS) return;
    const float* a = attn + (size_t)row * 256;
    float s = 0.f;
    for (int k = lane; k < 256; k += 32) {
        float v = a[k];
        s += v * v;
    }
#pragma unroll
    for (int off = 16; off; off >>= 1) s += __shfl_xor_sync(0xffffffffu, s, off);
    if (lane == 0) irms[row] = rsqrtf(s * (1.f / 256.f) + 1e-6f);
}

// ============================================================================
extern "C" void kernel_launch(void* const* d_in, const int* in_sizes, int n_in,
                              void* d_out, int out_size)
{
    const float* x      = (const float*)d_in[0];
    const float* W_qkv  = (const float*)d_in[1];
    const float* w_qn   = (const float*)d_in[2];
    const float* w_kn   = (const float*)d_in[3];
    const float* W_wp   = (const float*)d_in[4];
    const float* b_wp   = (const float*)d_in[5];
    const float* w_on   = (const float*)d_in[6];
    const float* W_out  = (const float*)d_in[7];
    const float* W_gate = (const float*)d_in[8];
    const float* b_gate = (const float*)d_in[9];
    float* out = (float*)d_out;

    float *vf, *wd, *sh, *attn, *irms;
    __half *xh, *xl, *qh, *ql, *kh, *vh, *vl, *mh, *ml, *wq, *wg, *wo;
    cudaGetSymbolAddress((void**)&vf, g_vf);
    cudaGetSymbolAddress((void**)&wd, g_width);
    cudaGetSymbolAddress((void**)&sh, g_sharp);
    cudaGetSymbolAddress((void**)&attn, g_attn);
    cudaGetSymbolAddress((void**)&irms, g_irms);
    cudaGetSymbolAddress((void**)&xh, g_xh);
    cudaGetSymbolAddress((void**)&xl, g_xl);
    cudaGetSymbolAddress((void**)&qh, g_qh);
    cudaGetSymbolAddress((void**)&ql, g_ql);
    cudaGetSymbolAddress((void**)&kh, g_kh);
    cudaGetSymbolAddress((void**)&vh, g_vh);
    cudaGetSymbolAddress((void**)&vl, g_vl);
    cudaGetSymbolAddress((void**)&mh, g_mh);
    cudaGetSymbolAddress((void**)&ml, g_ml);
    cudaGetSymbolAddress((void**)&wq, g_wq);
    cudaGetSymbolAddress((void**)&wg, g_wg);
    cudaGetSymbolAddress((void**)&wo, g_wo);

    cudaFuncSetAttribute(attn_k, cudaFuncAttributeMaxDynamicSharedMemorySize, SMEM_AT);
    const int SMEM_TC = 8 * 32 * CSTR * 4;   // 69,632 B
    cudaFuncSetAttribute(tc_gemm<0>, cudaFuncAttributeMaxDynamicSharedMemorySize, SMEM_TC);
    cudaFuncSetAttribute(tc_gemm<1>, cudaFuncAttributeMaxDynamicSharedMemorySize, SMEM_TC);
    cudaFuncSetAttribute(tc_gemm<2>, cudaFuncAttributeMaxDynamicSharedMemorySize, SMEM_TC);

    // 0) operand prep
    prep_x_k<<<NROWS / 8, 256>>>(x, W_wp, b_wp, xh, xl, wd, sh);
    prep_w_k<<<1280, 256>>>(W_qkv, W_gate, W_out, wq, wg, wo);

    // 1) qkv GEMM + fused silu/rmsnorm/rope -> qh/ql/kh fp16, vf fp32, vh/vl
    tc_gemm<0><<<dim3(6, 64), 256, SMEM_TC>>>(xh, xl, wq, nullptr, 0,
                                              nullptr, nullptr, nullptr, nullptr,
                                              w_qn, w_kn, qh, ql, kh, vf, vh, vl);
    // 2) local attention (tensor cores)
    attn_k<<<dim3(64, HEADS, 2), 256, SMEM_AT>>>(qh, ql, kh, vh, wd, sh, attn);
    // 3) inv-rms of attention output
    irms_k<<<NROWS / 8, 256>>>(attn, irms);
    // 4) gate GEMM + merge epilogue -> merged fp16 split
    tc_gemm<1><<<dim3(2, 64), 256, SMEM_TC>>>(vh, vl, wg, nullptr, 0,
                                              b_gate, attn, irms, w_on,
                                              nullptr, nullptr,
                                              nullptr, nullptr, nullptr, vf,
                                              mh, ml);
    // 5) out = silu(merged @ W_out)
    tc_gemm<2><<<dim3(2, 64), 256, SMEM_TC>>>(mh, ml, wo, out, 256,
                                              nullptr, nullptr, nullptr, nullptr,
                                              nullptr, nullptr,
                                              nullptr, nullptr, nullptr, nullptr,
                                              nullptr, nullptr);
}

// round 11
// speedup vs baseline: 1.4274x; 1.0395x over previous
#include <cuda_runtime.h>
#include <cuda_fp16.h>
#include <mma.h>
#include <math.h>
#include <stdint.h>

using namespace nvcuda;

#define NROWS 8192   // B*Hs*Ws = 2*64*64
#define CDIM  256
#define HEADS 4
#define HD    64
#define GRIDW 64     // Hs = Ws
#define ASTR  40     // gemm staging smem stride (halves) -> 80B rows, LDSM conflict-free
#define CSTR  68     // gemm epilogue smem stride (fp32)
#define TILE_H (128 * ASTR)

// attn smem layout (bytes)
#define VH_B   0          // Vh fp16 [208][72]
#define KH_B   29952      // Kh fp16 [208][72]   (inside S region, freed before S store)
#define QH_B   59904      // Qh fp16 [64][72]
#define QL_B   69120      // Ql fp16 [64][72]
#define S_B    29952      // S fp32 [64][216]  (A fp16 split in-place; O fp32 after)
#define SMEM_AT 85248

// -------- scratch (no allocations allowed) --------
__device__ __align__(256) float g_vf[NROWS * CDIM];
__device__ __align__(256) float g_width[NROWS * HEADS];
__device__ __align__(256) float g_sharp[NROWS * HEADS];
__device__ __align__(256) float g_attn[NROWS * CDIM];
__device__ __align__(256) float g_irms[NROWS];
// fp16 operands
__device__ __align__(256) __half g_xh[NROWS * 256];
__device__ __align__(256) __half g_xl[NROWS * 256];
__device__ __align__(256) __half g_qh[NROWS * 256];
__device__ __align__(256) __half g_ql[NROWS * 256];
__device__ __align__(256) __half g_kh[NROWS * 256];
__device__ __align__(256) __half g_vh[NROWS * 256];
__device__ __align__(256) __half g_vl[NROWS * 256];
__device__ __align__(256) __half g_mh[NROWS * 256];
__device__ __align__(256) __half g_ml[NROWS * 256];
// weights transposed to [N][K] fp16
__device__ __align__(256) __half g_wq[768 * 256];
__device__ __align__(256) __half g_wg[256 * 256];
__device__ __align__(256) __half g_wo[256 * 256];

__device__ __forceinline__ float sigm(float x) { return 1.f / (1.f + expf(-x)); }
__device__ __forceinline__ float silu(float x) { return x / (1.f + expf(-x)); }

// ============================================================================
// prep 1: per-row — fp16 split of x AND width/sharpness projection (warp/row)
// ============================================================================
__global__ __launch_bounds__(256) void prep_x_k(
    const float* __restrict__ x, const float* __restrict__ W,
    const float* __restrict__ bias,
    __half* __restrict__ xh, __half* __restrict__ xl,
    float* __restrict__ width, float* __restrict__ sharp)
{
    int row = (blockIdx.x * 256 + threadIdx.x) >> 5;
    int lane = threadIdx.x & 31;
    if (row >= NROWS) return;
    const float* xr = x + (size_t)row * 256;
    float acc[8] = {0, 0, 0, 0, 0, 0, 0, 0};
#pragma unroll
    for (int i = 0; i < 8; i++) {
        int k = lane + 32 * i;
        float v = xr[k];
        __half h = __float2half(v);
        xh[row * 256 + k] = h;
        xl[row * 256 + k] = __float2half(v - __half2float(h));
#pragma unroll
        for (int j = 0; j < 8; j++) acc[j] += v * W[k * 8 + j];
    }
#pragma unroll
    for (int off = 16; off; off >>= 1)
#pragma unroll
        for (int j = 0; j < 8; j++) acc[j] += __shfl_xor_sync(0xffffffffu, acc[j], off);
    if (lane == 0) {
#pragma unroll
        for (int j = 0; j < 4; j++) {
            float wr = silu(acc[j] + bias[j]);
            width[row * 4 + j] = sigm(wr) * 4.2426406871192851f + 0.5f;
            float sr = silu(acc[4 + j] + bias[4 + j]);
            sharp[row * 4 + j] = sigm(sr) * 9.5f + 0.5f;
        }
    }
}

// ============================================================================
// prep 2: weights: W [K,N] fp32 -> Wt [N,K] fp16, 32x32 smem-tiled transpose.
// 320 tiles: Wq 8x24=192, Wg 8x8=64, Wo 8x8=64. Block = 32x8 threads.
// ============================================================================
__global__ __launch_bounds__(256) void prep_w_k(
    const float* __restrict__ Wq, const float* __restrict__ Wg,
    const float* __restrict__ Wo,
    __half* __restrict__ tq, __half* __restrict__ tg, __half* __restrict__ to_)
{
    __shared__ float sm[32][33];
    int t = blockIdx.x;
    const float* W;
    __half* dst;
    int N, tk, tn;
    if (t < 192)      { W = Wq; dst = tq; N = 768; tk = t / 24; tn = t % 24; }
    else if (t < 256) { int u = t - 192; W = Wg; dst = tg; N = 256; tk = u / 8; tn = u % 8; }
    else              { int u = t - 256; W = Wo; dst = to_; N = 256; tk = u / 8; tn = u % 8; }
    const int tx = threadIdx.x & 31, ty = threadIdx.x >> 5;
    const int k0 = tk * 32, n0 = tn * 32;
#pragma unroll
    for (int i = 0; i < 4; i++)
        sm[ty + i * 8][tx] = W[(size_t)(k0 + ty + i * 8) * N + n0 + tx];
    __syncthreads();
#pragma unroll
    for (int i = 0; i < 4; i++)
        dst[(size_t)(n0 + ty + i * 8) * 256 + k0 + tx] = __float2half(sm[tx][ty + i * 8]);
}

// ============================================================================
// Tensor-core GEMM (wmma fp16, fp32 accum), 2-term split D = Ah*B + Al*B.
// CTA = 128x128, 8 warps (4x2), warp tile 32x64, 2 CTAs/SM.
// MODE 0 (qkv): q,k: silu->rmsnorm->rope -> q fp16 split (qh,ql), k fp16 (kh)
//               v: silu -> vf fp32 + fp16 split vh/vl
// MODE 1 (gate): merged = g*vf + (1-g)*attn*irms*won -> fp16 split mh/ml
// MODE 2 (out):  C = silu(acc) fp32
// ============================================================================
template <int MODE>
__global__ __launch_bounds__(256, 2) void tc_gemm(
    const __half* __restrict__ Ah, const __half* __restrict__ Al,
    const __half* __restrict__ Bh,
    float* __restrict__ Cp, int ldc,
    const float* __restrict__ bias, const float* __restrict__ attn,
    const float* __restrict__ irms, const float* __restrict__ won,
    const float* __restrict__ wqn, const float* __restrict__ wkn,
    __half* __restrict__ qh_o, __half* __restrict__ ql_o, __half* __restrict__ kh_o,
    float* __restrict__ vf,
    __half* __restrict__ so_h, __half* __restrict__ so_l)
{
    extern __shared__ char smem[];
    const int tid = threadIdx.x, wid = tid >> 5, lane = tid & 31;
    const int n0 = blockIdx.x * 128, m0 = blockIdx.y * 128;
    const int wm = wid & 3, wn = wid >> 2;

    __half* stg = (__half*)smem;

    wmma::fragment<wmma::accumulator, 16, 16, 16, float> acc[2][4];
#pragma unroll
    for (int mi = 0; mi < 2; mi++)
#pragma unroll
        for (int ni = 0; ni < 4; ni++) wmma::fill_fragment(acc[mi][ni], 0.f);

    for (int kc = 0; kc < 8; kc++) {
#pragma unroll
        for (int it = 0; it < 6; it++) {
            int idx = tid + it * 256;
            int which = idx >> 9, t = idx & 511;
            int row = t >> 2, c8 = (t & 3) << 3;
            const __half* gp;
            if (which == 0)      gp = Ah + (size_t)(m0 + row) * 256 + kc * 32 + c8;
            else if (which == 1) gp = Al + (size_t)(m0 + row) * 256 + kc * 32 + c8;
            else                 gp = Bh + (size_t)(n0 + row) * 256 + kc * 32 + c8;
            *(uint4*)&stg[which * TILE_H + row * ASTR + c8] = *(const uint4*)gp;
        }
        __syncthreads();

        const __half* Ash = stg;
        const __half* Asl = stg + TILE_H;
        const __half* Bsh = stg + 2 * TILE_H;

#pragma unroll
        for (int kk = 0; kk < 32; kk += 16) {
            wmma::fragment<wmma::matrix_b, 16, 16, 16, __half, wmma::col_major> bh[4];
#pragma unroll
            for (int ni = 0; ni < 4; ni++)
                wmma::load_matrix_sync(bh[ni], &Bsh[(wn * 64 + ni * 16) * ASTR + kk], ASTR);
#pragma unroll
            for (int mi = 0; mi < 2; mi++) {
                wmma::fragment<wmma::matrix_a, 16, 16, 16, __half, wmma::row_major> ah, al;
                wmma::load_matrix_sync(ah, &Ash[(wm * 32 + mi * 16) * ASTR + kk], ASTR);
                wmma::load_matrix_sync(al, &Asl[(wm * 32 + mi * 16) * ASTR + kk], ASTR);
#pragma unroll
                for (int ni = 0; ni < 4; ni++) {
                    wmma::mma_sync(acc[mi][ni], ah, bh[ni], acc[mi][ni]);
                    wmma::mma_sync(acc[mi][ni], al, bh[ni], acc[mi][ni]);
                }
            }
        }
        __syncthreads();
    }

    float* Cs = (float*)smem;
    float* Cw = Cs + wid * 32 * CSTR;
#pragma unroll
    for (int mi = 0; mi < 2; mi++)
#pragma unroll
        for (int ni = 0; ni < 4; ni++)
            wmma::store_matrix_sync(&Cw[mi * 16 * CSTR + ni * 16],
                                    acc[mi][ni], CSTR, wmma::mem_row_major);
    __syncwarp();

    const int nb2 = n0 + wn * 64;

    if (MODE == 0) {
        if (nb2 < 512) {
            const bool isq = (nb2 < 256);
            const int h = (isq ? nb2 : nb2 - 256) >> 6;
            const float* wn_ = isq ? wqn : wkn;
            {
                float ss = 0.f;
                float* rp = Cw + lane * CSTR;
#pragma unroll
                for (int c = 0; c < 64; c++) {
                    float v = silu(rp[c]);
                    ss += v * v;
                }
                float rinv = rsqrtf(ss * (1.f / 64.f) + 1e-6f);
#pragma unroll
                for (int c = 0; c < 32; c++) {
                    float q1 = silu(rp[c]) * rinv * wn_[c];
                    float q2 = silu(rp[c + 32]) * rinv * wn_[c + 32];
                    float freq = expf(-9.210340371976184f * (float)c * (1.f / 32.f));
                    float ang = (float)h * freq;
                    float cs = cosf(ang), sn = sinf(ang);
                    rp[c] = q1 * cs - q2 * sn;
                    rp[c + 32] = q1 * sn + q2 * cs;
                }
            }
            __syncwarp();
            for (int i = lane; i < 2048; i += 32) {
                int r = i >> 6, c = i & 63;
                int m = m0 + wm * 32 + r;
                float v = Cw[r * CSTR + c];
                int o = m * 256 + h * 64 + c;
                if (isq) {
                    __half hh = __float2half(v);
                    qh_o[o] = hh;
                    ql_o[o] = __float2half(v - __half2float(hh));
                } else {
                    kh_o[o] = __float2half(v);
                }
            }
        } else {
            for (int i = lane; i < 2048; i += 32) {
                int r = i >> 6, c = i & 63;
                int m = m0 + wm * 32 + r;
                int n = nb2 - 512 + c;
                float s = silu(Cw[r * CSTR + c]);
                vf[m * 256 + n] = s;
                __half hh = __float2half(s);
                so_h[m * 256 + n] = hh;
                so_l[m * 256 + n] = __float2half(s - __half2float(hh));
            }
        }
    } else if (MODE == 1) {
        for (int i = lane; i < 2048; i += 32) {
            int r = i >> 6, c = i & 63;
            int m = m0 + wm * 32 + r;
            int n = nb2 + c;
            float v = Cw[r * CSTR + c];
            float g = sigm(silu(v + bias[n]));
            float vv = vf[(size_t)m * 256 + n];
            float o = attn[(size_t)m * 256 + n] * irms[m] * won[n];
            float merged = g * vv + (1.f - g) * o;
            __half hh = __float2half(merged);
            so_h[m * 256 + n] = hh;
            so_l[m * 256 + n] = __float2half(merged - __half2float(hh));
        }
    } else {
        for (int i = lane; i < 2048; i += 32) {
            int r = i >> 6, c = i & 63;
            int m = m0 + wm * 32 + r;
            int n = nb2 + c;
            Cp[(size_t)m * ldc + n] = silu(Cw[r * CSTR + c]);
        }
    }
}

// ============================================================================
// Local attention via wmma:
//   S[64,208] = (Qh+Ql)[64,64] @ Kh^T    (q fp16 split, k fp16)
//   softmax over each query's 49-window (mask), A = attn weights fp16 split
//   O[64,64]  = (Ah+Al)[64,208] @ Vh[208,64]
// Block = (8x8 tile, head, batch), 256 threads, 2 CTAs/SM.
// ============================================================================
__global__ __launch_bounds__(256, 2) void attn_k(
    const __half* __restrict__ gqh, const __half* __restrict__ gql,
    const __half* __restrict__ gkh, const __half* __restrict__ gvh,
    const float* __restrict__ width, const float* __restrict__ sharp,
    float* __restrict__ out)
{
    extern __shared__ char smem[];
    __half* Vh = (__half*)(smem + VH_B);   // [208][72]
    __half* Kh = (__half*)(smem + KH_B);   // [208][72]
    __half* Qh = (__half*)(smem + QH_B);   // [64][72]
    __half* Ql = (__half*)(smem + QL_B);   // [64][72]
    float*  S  = (float*)(smem + S_B);     // [64][216]

    const int tile = blockIdx.x, h = blockIdx.y, b = blockIdx.z;
    const int ty0 = (tile >> 3) << 3;
    const int tx0 = (tile & 7) << 3;
    const int tid = threadIdx.x, wid = tid >> 5, lane = tid & 31;

    const uint4 zero4 = make_uint4(0, 0, 0, 0);
    for (int idx = tid; idx < 4352; idx += 256) {
        int job = idx >> 3, c = (idx & 7) << 3;
        uint4 val = zero4;
        __half* dst;
        if (job < 416) {
            int isv = job >= 208;
            int sp = isv ? job - 208 : job;
            dst = (isv ? Vh : Kh) + sp * 72 + c;
            if (sp < 196) {
                int yy = ty0 - 3 + sp / 14;
                int xx = tx0 - 3 + sp % 14;
                if (yy >= 0 && yy < GRIDW && xx >= 0 && xx < GRIDW) {
                    int r = (b * GRIDW + yy) * GRIDW + xx;
                    val = *(const uint4*)&(isv ? gvh : gkh)[(size_t)r * 256 + h * 64 + c];
                }
            }
        } else {
            int r0 = job - 416;
            int isl = r0 >= 64;
            int p = r0 & 63;
            dst = (isl ? Ql : Qh) + p * 72 + c;
            int r = (b * GRIDW + ty0 + (p >> 3)) * GRIDW + tx0 + (p & 7);
            val = *(const uint4*)&(isl ? gql : gqh)[(size_t)r * 256 + h * 64 + c];
        }
        *(uint4*)dst = val;
    }
    __syncthreads();

    const int wm = wid & 3, wn = wid >> 2;

    // ---- QK MMA ----
    {
        const int JN0 = wn * 7, NJ = wn ? 6 : 7;
        wmma::fragment<wmma::accumulator, 16, 16, 16, float> sacc[7];
#pragma unroll
        for (int j = 0; j < 7; j++) wmma::fill_fragment(sacc[j], 0.f);
#pragma unroll
        for (int kt = 0; kt < 4; kt++) {
            wmma::fragment<wmma::matrix_a, 16, 16, 16, __half, wmma::row_major> aqh, aql;
            wmma::load_matrix_sync(aqh, &Qh[wm * 16 * 72 + kt * 16], 72);
            wmma::load_matrix_sync(aql, &Ql[wm * 16 * 72 + kt * 16], 72);
            for (int j = 0; j < NJ; j++) {
                wmma::fragment<wmma::matrix_b, 16, 16, 16, __half, wmma::col_major> bk;
                wmma::load_matrix_sync(bk, &Kh[(JN0 + j) * 16 * 72 + kt * 16], 72);
                wmma::mma_sync(sacc[j], aqh, bk, sacc[j]);
                wmma::mma_sync(sacc[j], aql, bk, sacc[j]);
            }
        }
        __syncthreads();
        for (int j = 0; j < NJ; j++)
            wmma::store_matrix_sync(&S[wm * 16 * 216 + (JN0 + j) * 16], sacc[j], 216,
                                    wmma::mem_row_major);
    }
    __syncthreads();

    // ---- softmax + A split (in-place over S rows) ----
    {
        const int p = tid >> 2, sub = tid & 3;
        const int py = p >> 3, px = p & 7;
        const int row = (b * GRIDW + ty0 + py) * GRIDW + tx0 + px;
        const float wd = width[row * 4 + h];
        const float sh = sharp[row * 4 + h];
        float* srow = S + p * 216;

        float sr[13];
#pragma unroll
        for (int j = 0; j < 13; j++) {
            int w = sub + 4 * j;
            if (w < 49) {
                int wy = w / 7, wx = w % 7;
                float dy = (float)(wy - 3), dx = (float)(wx - 3);
                float rd = sqrtf(dy * dy + dx * dx);
                float soft = sigm((wd - rd) * sh);
                sr[j] = srow[(py + wy) * 14 + px + wx] * 0.125f - (1.f - soft) * 10000.f;
            } else {
                sr[j] = -1e30f;
            }
        }
        float mx = sr[0];
#pragma unroll
        for (int j = 1; j < 13; j++) mx = fmaxf(mx, sr[j]);
        mx = fmaxf(mx, __shfl_xor_sync(0xffffffffu, mx, 1));
        mx = fmaxf(mx, __shfl_xor_sync(0xffffffffu, mx, 2));
        float sum = 0.f;
#pragma unroll
        for (int j = 0; j < 13; j++) {
            float e = expf(sr[j] - mx);
            sr[j] = e;
            sum += e;
        }
        sum += __shfl_xor_sync(0xffffffffu, sum, 1);
        sum += __shfl_xor_sync(0xffffffffu, sum, 2);
        float inv = 1.f / sum;

        __syncwarp();
        float2* zrow = (float2*)srow;
#pragma unroll
        for (int i = 0; i < 27; i++) zrow[sub * 27 + i] = make_float2(0.f, 0.f);
        __syncwarp();
        __half* ah_row = (__half*)srow;
        __half* al_row = ah_row + 216;
#pragma unroll
        for (int j = 0; j < 13; j++) {
            int w = sub + 4 * j;
            if (w < 49) {
                int hi = (py + w / 7) * 14 + px + w % 7;
                float a = sr[j] * inv;
                __half hh = __float2half(a);
                ah_row[hi] = hh;
                al_row[hi] = __float2half(a - __half2float(hh));
            }
        }
    }
    __syncthreads();

    // ---- AV MMA ----
    {
        const __half* Ahp = (const __half*)(smem + S_B);
        const __half* Alp = Ahp + 216;
        wmma::fragment<wmma::accumulator, 16, 16, 16, float> oacc[2];
        wmma::fill_fragment(oacc[0], 0.f);
        wmma::fill_fragment(oacc[1], 0.f);
        for (int kt = 0; kt < 13; kt++) {
            wmma::fragment<wmma::matrix_a, 16, 16, 16, __half, wmma::row_major> fah, fal;
            wmma::load_matrix_sync(fah, &Ahp[wm * 16 * 432 + kt * 16], 432);
            wmma::load_matrix_sync(fal, &Alp[wm * 16 * 432 + kt * 16], 432);
#pragma unroll
            for (int ni = 0; ni < 2; ni++) {
                wmma::fragment<wmma::matrix_b, 16, 16, 16, __half, wmma::row_major> bv;
                wmma::load_matrix_sync(bv, &Vh[kt * 16 * 72 + wn * 32 + ni * 16], 72);
                wmma::mma_sync(oacc[ni], fah, bv, oacc[ni]);
                wmma::mma_sync(oacc[ni], fal, bv, oacc[ni]);
            }
        }
        __syncthreads();
        float* O = (float*)(smem + S_B);
#pragma unroll
        for (int ni = 0; ni < 2; ni++)
            wmma::store_matrix_sync(&O[wm * 16 * 72 + wn * 32 + ni * 16], oacc[ni], 72,
                                    wmma::mem_row_major);
    }
    __syncthreads();

    {
        const float* O = (const float*)(smem + S_B);
        for (int idx = tid; idx < 1024; idx += 256) {
            int p = idx >> 4, d4 = (idx & 15) << 2;
            int r = (b * GRIDW + ty0 + (p >> 3)) * GRIDW + tx0 + (p & 7);
            *(float4*)&out[(size_t)r * 256 + h * 64 + d4] = *(const float4*)&O[p * 72 + d4];
        }
    }
}

// ============================================================================
// inv-RMS per row of attention output.
// ============================================================================
__global__ __launch_bounds__(256) void irms_k(
    const float* __restrict__ attn, float* __restrict__ irms)
{
    int row = (blockIdx.x * 256 + threadIdx.x) >> 5;
    int lane = threadIdx.x & 31;
    if (row >= NROWS) return;
    const float* a = attn + (size_t)row * 256;
    float s = 0.f;
    for (int k = lane; k < 256; k += 32) {
        float v = a[k];
        s += v * v;
    }
#pragma unroll
    for (int off = 16; off; off >>= 1) s += __shfl_xor_sync(0xffffffffu, s, off);
    if (lane == 0) irms[row] = rsqrtf(s * (1.f / 256.f) + 1e-6f);
}

// ============================================================================
extern "C" void kernel_launch(void* const* d_in, const int* in_sizes, int n_in,
                              void* d_out, int out_size)
{
    const float* x      = (const float*)d_in[0];
    const float* W_qkv  = (const float*)d_in[1];
    const float* w_qn   = (const float*)d_in[2];
    const float* w_kn   = (const float*)d_in[3];
    const float* W_wp   = (const float*)d_in[4];
    const float* b_wp   = (const float*)d_in[5];
    const float* w_on   = (const float*)d_in[6];
    const float* W_out  = (const float*)d_in[7];
    const float* W_gate = (const float*)d_in[8];
    const float* b_gate = (const float*)d_in[9];
    float* out = (float*)d_out;

    float *vf, *wd, *sh, *attn, *irms;
    __half *xh, *xl, *qh, *ql, *kh, *vh, *vl, *mh, *ml, *wq, *wg, *wo;
    cudaGetSymbolAddress((void**)&vf, g_vf);
    cudaGetSymbolAddress((void**)&wd, g_width);
    cudaGetSymbolAddress((void**)&sh, g_sharp);
    cudaGetSymbolAddress((void**)&attn, g_attn);
    cudaGetSymbolAddress((void**)&irms, g_irms);
    cudaGetSymbolAddress((void**)&xh, g_xh);
    cudaGetSymbolAddress((void**)&xl, g_xl);
    cudaGetSymbolAddress((void**)&qh, g_qh);
    cudaGetSymbolAddress((void**)&ql, g_ql);
    cudaGetSymbolAddress((void**)&kh, g_kh);
    cudaGetSymbolAddress((void**)&vh, g_vh);
    cudaGetSymbolAddress((void**)&vl, g_vl);
    cudaGetSymbolAddress((void**)&mh, g_mh);
    cudaGetSymbolAddress((void**)&ml, g_ml);
    cudaGetSymbolAddress((void**)&wq, g_wq);
    cudaGetSymbolAddress((void**)&wg, g_wg);
    cudaGetSymbolAddress((void**)&wo, g_wo);

    cudaFuncSetAttribute(attn_k, cudaFuncAttributeMaxDynamicSharedMemorySize, SMEM_AT);
    const int SMEM_TC = 8 * 32 * CSTR * 4;   // 69,632 B (staging 30,720 aliased)
    cudaFuncSetAttribute(tc_gemm<0>, cudaFuncAttributeMaxDynamicSharedMemorySize, SMEM_TC);
    cudaFuncSetAttribute(tc_gemm<1>, cudaFuncAttributeMaxDynamicSharedMemorySize, SMEM_TC);
    cudaFuncSetAttribute(tc_gemm<2>, cudaFuncAttributeMaxDynamicSharedMemorySize, SMEM_TC);

    // 0) operand prep
    prep_x_k<<<NROWS / 8, 256>>>(x, W_wp, b_wp, xh, xl, wd, sh);
    prep_w_k<<<320, 256>>>(W_qkv, W_gate, W_out, wq, wg, wo);

    // 1) qkv GEMM + fused silu/rmsnorm/rope -> qh/ql/kh fp16, vf fp32, vh/vl
    tc_gemm<0><<<dim3(6, 64), 256, SMEM_TC>>>(xh, xl, wq, nullptr, 0,
                                              nullptr, nullptr, nullptr, nullptr,
                                              w_qn, w_kn, qh, ql, kh, vf, vh, vl);
    // 2) local attention (tensor cores)
    attn_k<<<dim3(64, HEADS, 2), 256, SMEM_AT>>>(qh, ql, kh, vh, wd, sh, attn);
    // 3) inv-rms of attention output
    irms_k<<<NROWS / 8, 256>>>(attn, irms);
    // 4) gate GEMM + merge epilogue -> merged fp16 split
    tc_gemm<1><<<dim3(2, 64), 256, SMEM_TC>>>(vh, vl, wg, nullptr, 0,
                                              b_gate, attn, irms, w_on,
                                              nullptr, nullptr,
                                              nullptr, nullptr, nullptr, vf,
                                              mh, ml);
    // 5) out = silu(merged @ W_out)
    tc_gemm<2><<<dim3(2, 64), 256, SMEM_TC>>>(mh, ml, wo, out, 256,
                                              nullptr, nullptr, nullptr, nullptr,
                                              nullptr, nullptr,
                                              nullptr, nullptr, nullptr, nullptr,
                                              nullptr, nullptr);
}

// round 12
// speedup vs baseline: 1.5344x; 1.0750x over previous
#include <cuda_runtime.h>
#include <cuda_fp16.h>
#include <mma.h>
#include <math.h>
#include <stdint.h>

using namespace nvcuda;

#define NROWS 8192   // B*Hs*Ws = 2*64*64
#define CDIM  256
#define HEADS 4
#define HD    64
#define GRIDW 64     // Hs = Ws
#define ASTR  40     // gemm staging smem stride (halves) -> 80B rows
#define CSTR  68     // gemm epilogue smem stride (fp32)
#define TILE_H (128 * ASTR)

// attn smem layout (bytes)
#define VH_B   0          // Vh fp16 [208][72]
#define KH_B   29952      // Kh fp16 [208][72]   (inside S region, freed before S store)
#define QH_B   59904      // Qh fp16 [64][72]
#define QL_B   69120      // Ql fp16 [64][72]
#define S_B    29952      // S fp32 [64][216]  (A fp16 split in-place; O fp32 after)
#define SMEM_AT 85248

// -------- scratch (no allocations allowed) --------
__device__ __align__(256) float g_vf[NROWS * CDIM];
__device__ __align__(256) float g_width[NROWS * HEADS];
__device__ __align__(256) float g_sharp[NROWS * HEADS];
__device__ __align__(256) float g_attn[NROWS * CDIM];
__device__ __align__(256) float g_ssq[NROWS * HEADS];
// fp16 operands
__device__ __align__(256) __half g_xh[NROWS * 256];
__device__ __align__(256) __half g_xl[NROWS * 256];
__device__ __align__(256) __half g_qh[NROWS * 256];
__device__ __align__(256) __half g_ql[NROWS * 256];
__device__ __align__(256) __half g_kh[NROWS * 256];
__device__ __align__(256) __half g_vh[NROWS * 256];
__device__ __align__(256) __half g_mh[NROWS * 256];
// weights transposed to [N][K] fp16
__device__ __align__(256) __half g_wq[768 * 256];
__device__ __align__(256) __half g_wg[256 * 256];
__device__ __align__(256) __half g_wo[256 * 256];

__device__ __forceinline__ float sigm(float x) { return 1.f / (1.f + expf(-x)); }
__device__ __forceinline__ float silu(float x) { return x / (1.f + expf(-x)); }

// ============================================================================
// prep 1: per-row — fp16 split of x AND width/sharpness projection (warp/row)
// ============================================================================
__global__ __launch_bounds__(256) void prep_x_k(
    const float* __restrict__ x, const float* __restrict__ W,
    const float* __restrict__ bias,
    __half* __restrict__ xh, __half* __restrict__ xl,
    float* __restrict__ width, float* __restrict__ sharp)
{
    int row = (blockIdx.x * 256 + threadIdx.x) >> 5;
    int lane = threadIdx.x & 31;
    if (row >= NROWS) return;
    const float* xr = x + (size_t)row * 256;
    float acc[8] = {0, 0, 0, 0, 0, 0, 0, 0};
#pragma unroll
    for (int i = 0; i < 8; i++) {
        int k = lane + 32 * i;
        float v = xr[k];
        __half h = __float2half(v);
        xh[row * 256 + k] = h;
        xl[row * 256 + k] = __float2half(v - __half2float(h));
#pragma unroll
        for (int j = 0; j < 8; j++) acc[j] += v * W[k * 8 + j];
    }
#pragma unroll
    for (int off = 16; off; off >>= 1)
#pragma unroll
        for (int j = 0; j < 8; j++) acc[j] += __shfl_xor_sync(0xffffffffu, acc[j], off);
    if (lane == 0) {
#pragma unroll
        for (int j = 0; j < 4; j++) {
            float wr = silu(acc[j] + bias[j]);
            width[row * 4 + j] = sigm(wr) * 4.2426406871192851f + 0.5f;
            float sr = silu(acc[4 + j] + bias[4 + j]);
            sharp[row * 4 + j] = sigm(sr) * 9.5f + 0.5f;
        }
    }
}

// ============================================================================
// prep 2: weights: W [K,N] fp32 -> Wt [N,K] fp16, 32x32 smem-tiled transpose.
// ============================================================================
__global__ __launch_bounds__(256) void prep_w_k(
    const float* __restrict__ Wq, const float* __restrict__ Wg,
    const float* __restrict__ Wo,
    __half* __restrict__ tq, __half* __restrict__ tg, __half* __restrict__ to_)
{
    __shared__ float sm[32][33];
    int t = blockIdx.x;
    const float* W;
    __half* dst;
    int N, tk, tn;
    if (t < 192)      { W = Wq; dst = tq; N = 768; tk = t / 24; tn = t % 24; }
    else if (t < 256) { int u = t - 192; W = Wg; dst = tg; N = 256; tk = u / 8; tn = u % 8; }
    else              { int u = t - 256; W = Wo; dst = to_; N = 256; tk = u / 8; tn = u % 8; }
    const int tx = threadIdx.x & 31, ty = threadIdx.x >> 5;
    const int k0 = tk * 32, n0 = tn * 32;
#pragma unroll
    for (int i = 0; i < 4; i++)
        sm[ty + i * 8][tx] = W[(size_t)(k0 + ty + i * 8) * N + n0 + tx];
    __syncthreads();
#pragma unroll
    for (int i = 0; i < 4; i++)
        dst[(size_t)(n0 + ty + i * 8) * 256 + k0 + tx] = __float2half(sm[tx][ty + i * 8]);
}

// ============================================================================
// Tensor-core GEMM (wmma fp16, fp32 accum).
// TERMS=2: D = Ah*B + Al*B ;  TERMS=1: D = Ah*B.
// CTA = 128x128, 8 warps (4x2), warp tile 32x64, 2 CTAs/SM.
// MODE 0 (qkv, T2): q,k: silu->rmsnorm->rope -> qh/ql fp16 split, kh fp16
//                   v: silu -> vf fp32 + vh fp16
// MODE 1 (gate, T1): irms from ssq; merged = g*vf + (1-g)*attn*irms*won -> mh
// MODE 2 (out,  T1): C = silu(acc) fp32
// ============================================================================
template <int MODE, int TERMS>
__global__ __launch_bounds__(256, 2) void tc_gemm(
    const __half* __restrict__ Ah, const __half* __restrict__ Al,
    const __half* __restrict__ Bh,
    float* __restrict__ Cp, int ldc,
    const float* __restrict__ bias, const float* __restrict__ attn,
    const float* __restrict__ ssq, const float* __restrict__ won,
    const float* __restrict__ wqn, const float* __restrict__ wkn,
    __half* __restrict__ qh_o, __half* __restrict__ ql_o, __half* __restrict__ kh_o,
    float* __restrict__ vf,
    __half* __restrict__ so_h)
{
    extern __shared__ char smem[];
    const int tid = threadIdx.x, wid = tid >> 5, lane = tid & 31;
    const int n0 = blockIdx.x * 128, m0 = blockIdx.y * 128;
    const int wm = wid & 3, wn = wid >> 2;
    const int NTILES = TERMS + 1;

    __half* stg = (__half*)smem;

    wmma::fragment<wmma::accumulator, 16, 16, 16, float> acc[2][4];
#pragma unroll
    for (int mi = 0; mi < 2; mi++)
#pragma unroll
        for (int ni = 0; ni < 4; ni++) wmma::fill_fragment(acc[mi][ni], 0.f);

    for (int kc = 0; kc < 8; kc++) {
#pragma unroll
        for (int it = 0; it < 2 * NTILES; it++) {
            int idx = tid + it * 256;
            int which = idx >> 9, t = idx & 511;
            int row = t >> 2, c8 = (t & 3) << 3;
            const __half* gp;
            if (which == 0)                       gp = Ah + (size_t)(m0 + row) * 256 + kc * 32 + c8;
            else if (TERMS == 2 && which == 1)    gp = Al + (size_t)(m0 + row) * 256 + kc * 32 + c8;
            else                                  gp = Bh + (size_t)(n0 + row) * 256 + kc * 32 + c8;
            *(uint4*)&stg[which * TILE_H + row * ASTR + c8] = *(const uint4*)gp;
        }
        __syncthreads();

        const __half* Ash = stg;
        const __half* Asl = stg + TILE_H;
        const __half* Bsh = stg + (NTILES - 1) * TILE_H;

#pragma unroll
        for (int kk = 0; kk < 32; kk += 16) {
            wmma::fragment<wmma::matrix_b, 16, 16, 16, __half, wmma::col_major> bh[4];
#pragma unroll
            for (int ni = 0; ni < 4; ni++)
                wmma::load_matrix_sync(bh[ni], &Bsh[(wn * 64 + ni * 16) * ASTR + kk], ASTR);
#pragma unroll
            for (int mi = 0; mi < 2; mi++) {
                wmma::fragment<wmma::matrix_a, 16, 16, 16, __half, wmma::row_major> ah;
                wmma::load_matrix_sync(ah, &Ash[(wm * 32 + mi * 16) * ASTR + kk], ASTR);
#pragma unroll
                for (int ni = 0; ni < 4; ni++)
                    wmma::mma_sync(acc[mi][ni], ah, bh[ni], acc[mi][ni]);
                if (TERMS == 2) {
                    wmma::fragment<wmma::matrix_a, 16, 16, 16, __half, wmma::row_major> al;
                    wmma::load_matrix_sync(al, &Asl[(wm * 32 + mi * 16) * ASTR + kk], ASTR);
#pragma unroll
                    for (int ni = 0; ni < 4; ni++)
                        wmma::mma_sync(acc[mi][ni], al, bh[ni], acc[mi][ni]);
                }
            }
        }
        __syncthreads();
    }

    float* Cs = (float*)smem;
    float* Cw = Cs + wid * 32 * CSTR;
#pragma unroll
    for (int mi = 0; mi < 2; mi++)
#pragma unroll
        for (int ni = 0; ni < 4; ni++)
            wmma::store_matrix_sync(&Cw[mi * 16 * CSTR + ni * 16],
                                    acc[mi][ni], CSTR, wmma::mem_row_major);
    __syncwarp();

    const int nb2 = n0 + wn * 64;

    if (MODE == 0) {
        if (nb2 < 512) {
            const bool isq = (nb2 < 256);
            const int h = (isq ? nb2 : nb2 - 256) >> 6;
            const float* wn_ = isq ? wqn : wkn;
            {
                float ss = 0.f;
                float* rp = Cw + lane * CSTR;
#pragma unroll
                for (int c = 0; c < 64; c++) {
                    float v = silu(rp[c]);
                    ss += v * v;
                }
                float rinv = rsqrtf(ss * (1.f / 64.f) + 1e-6f);
#pragma unroll
                for (int c = 0; c < 32; c++) {
                    float q1 = silu(rp[c]) * rinv * wn_[c];
                    float q2 = silu(rp[c + 32]) * rinv * wn_[c + 32];
                    float freq = expf(-9.210340371976184f * (float)c * (1.f / 32.f));
                    float ang = (float)h * freq;
                    float cs = cosf(ang), sn = sinf(ang);
                    rp[c] = q1 * cs - q2 * sn;
                    rp[c + 32] = q1 * sn + q2 * cs;
                }
            }
            __syncwarp();
            for (int i = lane; i < 2048; i += 32) {
                int r = i >> 6, c = i & 63;
                int m = m0 + wm * 32 + r;
                float v = Cw[r * CSTR + c];
                int o = m * 256 + h * 64 + c;
                if (isq) {
                    __half hh = __float2half(v);
                    qh_o[o] = hh;
                    ql_o[o] = __float2half(v - __half2float(hh));
                } else {
                    kh_o[o] = __float2half(v);
                }
            }
        } else {
            for (int i = lane; i < 2048; i += 32) {
                int r = i >> 6, c = i & 63;
                int m = m0 + wm * 32 + r;
                int n = nb2 - 512 + c;
                float s = silu(Cw[r * CSTR + c]);
                vf[m * 256 + n] = s;
                so_h[m * 256 + n] = __float2half(s);
            }
        }
    } else if (MODE == 1) {
        for (int i = lane; i < 2048; i += 32) {
            int r = i >> 6, c = i & 63;
            int m = m0 + wm * 32 + r;
            int n = nb2 + c;
            float v = Cw[r * CSTR + c];
            float g = sigm(silu(v + bias[n]));
            float vv = vf[(size_t)m * 256 + n];
            const float* sq = ssq + m * 4;
            float irms = rsqrtf((sq[0] + sq[1] + sq[2] + sq[3]) * (1.f / 256.f) + 1e-6f);
            float o = attn[(size_t)m * 256 + n] * irms * won[n];
            float merged = g * vv + (1.f - g) * o;
            so_h[m * 256 + n] = __float2half(merged);
        }
    } else {
        for (int i = lane; i < 2048; i += 32) {
            int r = i >> 6, c = i & 63;
            int m = m0 + wm * 32 + r;
            int n = nb2 + c;
            Cp[(size_t)m * ldc + n] = silu(Cw[r * CSTR + c]);
        }
    }
}

// ============================================================================
// Local attention via wmma (S = Q@K^T, masked softmax, O = A@V).
// Also emits per-(row,head) sum-of-squares for downstream rmsnorm.
// Block = (8x8 tile, head, batch), 256 threads, 2 CTAs/SM.
// ============================================================================
__global__ __launch_bounds__(256, 2) void attn_k(
    const __half* __restrict__ gqh, const __half* __restrict__ gql,
    const __half* __restrict__ gkh, const __half* __restrict__ gvh,
    const float* __restrict__ width, const float* __restrict__ sharp,
    float* __restrict__ out, float* __restrict__ ssq)
{
    extern __shared__ char smem[];
    __half* Vh = (__half*)(smem + VH_B);   // [208][72]
    __half* Kh = (__half*)(smem + KH_B);   // [208][72]
    __half* Qh = (__half*)(smem + QH_B);   // [64][72]
    __half* Ql = (__half*)(smem + QL_B);   // [64][72]
    float*  S  = (float*)(smem + S_B);     // [64][216]

    const int tile = blockIdx.x, h = blockIdx.y, b = blockIdx.z;
    const int ty0 = (tile >> 3) << 3;
    const int tx0 = (tile & 7) << 3;
    const int tid = threadIdx.x, wid = tid >> 5;

    const uint4 zero4 = make_uint4(0, 0, 0, 0);
    for (int idx = tid; idx < 4352; idx += 256) {
        int job = idx >> 3, c = (idx & 7) << 3;
        uint4 val = zero4;
        __half* dst;
        if (job < 416) {
            int isv = job >= 208;
            int sp = isv ? job - 208 : job;
            dst = (isv ? Vh : Kh) + sp * 72 + c;
            if (sp < 196) {
                int yy = ty0 - 3 + sp / 14;
                int xx = tx0 - 3 + sp % 14;
                if (yy >= 0 && yy < GRIDW && xx >= 0 && xx < GRIDW) {
                    int r = (b * GRIDW + yy) * GRIDW + xx;
                    val = *(const uint4*)&(isv ? gvh : gkh)[(size_t)r * 256 + h * 64 + c];
                }
            }
        } else {
            int r0 = job - 416;
            int isl = r0 >= 64;
            int p = r0 & 63;
            dst = (isl ? Ql : Qh) + p * 72 + c;
            int r = (b * GRIDW + ty0 + (p >> 3)) * GRIDW + tx0 + (p & 7);
            val = *(const uint4*)&(isl ? gql : gqh)[(size_t)r * 256 + h * 64 + c];
        }
        *(uint4*)dst = val;
    }
    __syncthreads();

    const int wm = wid & 3, wn = wid >> 2;

    // ---- QK MMA ----
    {
        const int JN0 = wn * 7, NJ = wn ? 6 : 7;
        wmma::fragment<wmma::accumulator, 16, 16, 16, float> sacc[7];
#pragma unroll
        for (int j = 0; j < 7; j++) wmma::fill_fragment(sacc[j], 0.f);
#pragma unroll
        for (int kt = 0; kt < 4; kt++) {
            wmma::fragment<wmma::matrix_a, 16, 16, 16, __half, wmma::row_major> aqh, aql;
            wmma::load_matrix_sync(aqh, &Qh[wm * 16 * 72 + kt * 16], 72);
            wmma::load_matrix_sync(aql, &Ql[wm * 16 * 72 + kt * 16], 72);
            for (int j = 0; j < NJ; j++) {
                wmma::fragment<wmma::matrix_b, 16, 16, 16, __half, wmma::col_major> bk;
                wmma::load_matrix_sync(bk, &Kh[(JN0 + j) * 16 * 72 + kt * 16], 72);
                wmma::mma_sync(sacc[j], aqh, bk, sacc[j]);
                wmma::mma_sync(sacc[j], aql, bk, sacc[j]);
            }
        }
        __syncthreads();
        for (int j = 0; j < NJ; j++)
            wmma::store_matrix_sync(&S[wm * 16 * 216 + (JN0 + j) * 16], sacc[j], 216,
                                    wmma::mem_row_major);
    }
    __syncthreads();

    // ---- softmax + A split (in-place over S rows) ----
    {
        const int p = tid >> 2, sub = tid & 3;
        const int py = p >> 3, px = p & 7;
        const int row = (b * GRIDW + ty0 + py) * GRIDW + tx0 + px;
        const float wd = width[row * 4 + h];
        const float sh = sharp[row * 4 + h];
        float* srow = S + p * 216;

        float sr[13];
#pragma unroll
        for (int j = 0; j < 13; j++) {
            int w = sub + 4 * j;
            if (w < 49) {
                int wy = w / 7, wx = w % 7;
                float dy = (float)(wy - 3), dx = (float)(wx - 3);
                float rd = sqrtf(dy * dy + dx * dx);
                float soft = sigm((wd - rd) * sh);
                sr[j] = srow[(py + wy) * 14 + px + wx] * 0.125f - (1.f - soft) * 10000.f;
            } else {
                sr[j] = -1e30f;
            }
        }
        float mx = sr[0];
#pragma unroll
        for (int j = 1; j < 13; j++) mx = fmaxf(mx, sr[j]);
        mx = fmaxf(mx, __shfl_xor_sync(0xffffffffu, mx, 1));
        mx = fmaxf(mx, __shfl_xor_sync(0xffffffffu, mx, 2));
        float sum = 0.f;
#pragma unroll
        for (int j = 0; j < 13; j++) {
            float e = expf(sr[j] - mx);
            sr[j] = e;
            sum += e;
        }
        sum += __shfl_xor_sync(0xffffffffu, sum, 1);
        sum += __shfl_xor_sync(0xffffffffu, sum, 2);
        float inv = 1.f / sum;

        __syncwarp();
        float2* zrow = (float2*)srow;
#pragma unroll
        for (int i = 0; i < 27; i++) zrow[sub * 27 + i] = make_float2(0.f, 0.f);
        __syncwarp();
        __half* ah_row = (__half*)srow;
        __half* al_row = ah_row + 216;
#pragma unroll
        for (int j = 0; j < 13; j++) {
            int w = sub + 4 * j;
            if (w < 49) {
                int hi = (py + w / 7) * 14 + px + w % 7;
                float a = sr[j] * inv;
                __half hh = __float2half(a);
                ah_row[hi] = hh;
                al_row[hi] = __float2half(a - __half2float(hh));
            }
        }
    }
    __syncthreads();

    // ---- AV MMA ----
    {
        const __half* Ahp = (const __half*)(smem + S_B);
        const __half* Alp = Ahp + 216;
        wmma::fragment<wmma::accumulator, 16, 16, 16, float> oacc[2];
        wmma::fill_fragment(oacc[0], 0.f);
        wmma::fill_fragment(oacc[1], 0.f);
        for (int kt = 0; kt < 13; kt++) {
            wmma::fragment<wmma::matrix_a, 16, 16, 16, __half, wmma::row_major> fah, fal;
            wmma::load_matrix_sync(fah, &Ahp[wm * 16 * 432 + kt * 16], 432);
            wmma::load_matrix_sync(fal, &Alp[wm * 16 * 432 + kt * 16], 432);
#pragma unroll
            for (int ni = 0; ni < 2; ni++) {
                wmma::fragment<wmma::matrix_b, 16, 16, 16, __half, wmma::row_major> bv;
                wmma::load_matrix_sync(bv, &Vh[kt * 16 * 72 + wn * 32 + ni * 16], 72);
                wmma::mma_sync(oacc[ni], fah, bv, oacc[ni]);
                wmma::mma_sync(oacc[ni], fal, bv, oacc[ni]);
            }
        }
        __syncthreads();
        float* O = (float*)(smem + S_B);
#pragma unroll
        for (int ni = 0; ni < 2; ni++)
            wmma::store_matrix_sync(&O[wm * 16 * 72 + wn * 32 + ni * 16], oacc[ni], 72,
                                    wmma::mem_row_major);
    }
    __syncthreads();

    // ---- write out + per-position sum-of-squares ----
    {
        const float* O = (const float*)(smem + S_B);
        for (int idx = tid; idx < 1024; idx += 256) {
            int p = idx >> 4, d4 = (idx & 15) << 2;
            int r = (b * GRIDW + ty0 + (p >> 3)) * GRIDW + tx0 + (p & 7);
            *(float4*)&out[(size_t)r * 256 + h * 64 + d4] = *(const float4*)&O[p * 72 + d4];
        }
        // ssq: 4 threads per position, 16 dims each
        int p = tid >> 2, qd = tid & 3;
        float s = 0.f;
#pragma unroll
        for (int i = 0; i < 16; i++) {
            float v = O[p * 72 + qd * 16 + i];
            s += v * v;
        }
        s += __shfl_xor_sync(0xffffffffu, s, 1);
        s += __shfl_xor_sync(0xffffffffu, s, 2);
        if (qd == 0) {
            int r = (b * GRIDW + ty0 + (p >> 3)) * GRIDW + tx0 + (p & 7);
            ssq[r * 4 + h] = s;
        }
    }
}

// ============================================================================
extern "C" void kernel_launch(void* const* d_in, const int* in_sizes, int n_in,
                              void* d_out, int out_size)
{
    const float* x      = (const float*)d_in[0];
    const float* W_qkv  = (const float*)d_in[1];
    const float* w_qn   = (const float*)d_in[2];
    const float* w_kn   = (const float*)d_in[3];
    const float* W_wp   = (const float*)d_in[4];
    const float* b_wp   = (const float*)d_in[5];
    const float* w_on   = (const float*)d_in[6];
    const float* W_out  = (const float*)d_in[7];
    const float* W_gate = (const float*)d_in[8];
    const float* b_gate = (const float*)d_in[9];
    float* out = (float*)d_out;

    float *vf, *wd, *sh, *attn, *ssq;
    __half *xh, *xl, *qh, *ql, *kh, *vh, *mh, *wq, *wg, *wo;
    cudaGetSymbolAddress((void**)&vf, g_vf);
    cudaGetSymbolAddress((void**)&wd, g_width);
    cudaGetSymbolAddress((void**)&sh, g_sharp);
    cudaGetSymbolAddress((void**)&attn, g_attn);
    cudaGetSymbolAddress((void**)&ssq, g_ssq);
    cudaGetSymbolAddress((void**)&xh, g_xh);
    cudaGetSymbolAddress((void**)&xl, g_xl);
    cudaGetSymbolAddress((void**)&qh, g_qh);
    cudaGetSymbolAddress((void**)&ql, g_ql);
    cudaGetSymbolAddress((void**)&kh, g_kh);
    cudaGetSymbolAddress((void**)&vh, g_vh);
    cudaGetSymbolAddress((void**)&mh, g_mh);
    cudaGetSymbolAddress((void**)&wq, g_wq);
    cudaGetSymbolAddress((void**)&wg, g_wg);
    cudaGetSymbolAddress((void**)&wo, g_wo);

    cudaFuncSetAttribute(attn_k, cudaFuncAttributeMaxDynamicSharedMemorySize, SMEM_AT);
    const int SMEM_TC = 8 * 32 * CSTR * 4;   // 69,632 B
    cudaFuncSetAttribute(tc_gemm<0, 2>, cudaFuncAttributeMaxDynamicSharedMemorySize, SMEM_TC);
    cudaFuncSetAttribute(tc_gemm<1, 1>, cudaFuncAttributeMaxDynamicSharedMemorySize, SMEM_TC);
    cudaFuncSetAttribute(tc_gemm<2, 1>, cudaFuncAttributeMaxDynamicSharedMemorySize, SMEM_TC);

    // 0) operand prep
    prep_x_k<<<NROWS / 8, 256>>>(x, W_wp, b_wp, xh, xl, wd, sh);
    prep_w_k<<<320, 256>>>(W_qkv, W_gate, W_out, wq, wg, wo);

    // 1) qkv GEMM (2-term) + fused silu/rmsnorm/rope -> qh/ql/kh, vf, vh
    tc_gemm<0, 2><<<dim3(6, 64), 256, SMEM_TC>>>(xh, xl, wq, nullptr, 0,
                                                 nullptr, nullptr, nullptr, nullptr,
                                                 w_qn, w_kn, qh, ql, kh, vf, vh);
    // 2) local attention (tensor cores) + ssq
    attn_k<<<dim3(64, HEADS, 2), 256, SMEM_AT>>>(qh, ql, kh, vh, wd, sh, attn, ssq);
    // 3) gate GEMM (1-term) + merge epilogue (irms from ssq) -> mh
    tc_gemm<1, 1><<<dim3(2, 64), 256, SMEM_TC>>>(vh, nullptr, wg, nullptr, 0,
                                                 b_gate, attn, ssq, w_on,
                                                 nullptr, nullptr,
                                                 nullptr, nullptr, nullptr, vf, mh);
    // 4) out = silu(merged @ W_out)  (1-term)
    tc_gemm<2, 1><<<dim3(2, 64), 256, SMEM_TC>>>(mh, nullptr, wo, out, 256,
                                                 nullptr, nullptr, nullptr, nullptr,
                                                 nullptr, nullptr,
                                                 nullptr, nullptr, nullptr, nullptr,
                                                 nullptr);
}

// round 13
// speedup vs baseline: 1.5542x; 1.0129x over previous
#include <cuda_runtime.h>
#include <cuda_fp16.h>
#include <mma.h>
#include <math.h>
#include <stdint.h>

using namespace nvcuda;

#define NROWS 8192   // B*Hs*Ws = 2*64*64
#define CDIM  256
#define HEADS 4
#define HD    64
#define GRIDW 64     // Hs = Ws
#define ASTR  40     // gemm staging smem stride (halves) -> 80B rows
#define CSTR  68     // gemm epilogue smem stride (fp32)
#define TILE_H (128 * ASTR)

// attn smem layout (bytes)
#define VH_B   0          // Vh fp16 [208][72]
#define KH_B   29952      // Kh fp16 [208][72]   (inside S region, freed before S store)
#define QH_B   59904      // Qh fp16 [64][72]
#define QL_B   69120      // Ql fp16 [64][72]
#define S_B    29952      // S fp32 [64][216]  (A fp16 in-place; O fp32 after)
#define SMEM_AT 85248

// -------- scratch (no allocations allowed) --------
__device__ __align__(256) float g_vf[NROWS * CDIM];
__device__ __align__(256) float g_width[NROWS * HEADS];
__device__ __align__(256) float g_sharp[NROWS * HEADS];
__device__ __align__(256) float g_attn[NROWS * CDIM];
__device__ __align__(256) float g_ssq[NROWS * HEADS];
// fp16 operands
__device__ __align__(256) __half g_xh[NROWS * 256];
__device__ __align__(256) __half g_xl[NROWS * 256];
__device__ __align__(256) __half g_qh[NROWS * 256];
__device__ __align__(256) __half g_ql[NROWS * 256];
__device__ __align__(256) __half g_kh[NROWS * 256];
__device__ __align__(256) __half g_vh[NROWS * 256];
__device__ __align__(256) __half g_mh[NROWS * 256];
// weights transposed to [N][K] fp16
__device__ __align__(256) __half g_wq[768 * 256];
__device__ __align__(256) __half g_wg[256 * 256];
__device__ __align__(256) __half g_wo[256 * 256];

__device__ __forceinline__ float sigm(float x) { return 1.f / (1.f + expf(-x)); }
__device__ __forceinline__ float silu(float x) { return x / (1.f + expf(-x)); }

// ============================================================================
// prep 1: per-row — fp16 split of x AND width/sharpness projection (warp/row)
// ============================================================================
__global__ __launch_bounds__(256) void prep_x_k(
    const float* __restrict__ x, const float* __restrict__ W,
    const float* __restrict__ bias,
    __half* __restrict__ xh, __half* __restrict__ xl,
    float* __restrict__ width, float* __restrict__ sharp)
{
    int row = (blockIdx.x * 256 + threadIdx.x) >> 5;
    int lane = threadIdx.x & 31;
    if (row >= NROWS) return;
    const float* xr = x + (size_t)row * 256;
    float acc[8] = {0, 0, 0, 0, 0, 0, 0, 0};
#pragma unroll
    for (int i = 0; i < 8; i++) {
        int k = lane + 32 * i;
        float v = xr[k];
        __half h = __float2half(v);
        xh[row * 256 + k] = h;
        xl[row * 256 + k] = __float2half(v - __half2float(h));
#pragma unroll
        for (int j = 0; j < 8; j++) acc[j] += v * W[k * 8 + j];
    }
#pragma unroll
    for (int off = 16; off; off >>= 1)
#pragma unroll
        for (int j = 0; j < 8; j++) acc[j] += __shfl_xor_sync(0xffffffffu, acc[j], off);
    if (lane == 0) {
#pragma unroll
        for (int j = 0; j < 4; j++) {
            float wr = silu(acc[j] + bias[j]);
            width[row * 4 + j] = sigm(wr) * 4.2426406871192851f + 0.5f;
            float sr = silu(acc[4 + j] + bias[4 + j]);
            sharp[row * 4 + j] = sigm(sr) * 9.5f + 0.5f;
        }
    }
}

// ============================================================================
// prep 2: weights: W [K,N] fp32 -> Wt [N,K] fp16, 32x32 smem-tiled transpose.
// ============================================================================
__global__ __launch_bounds__(256) void prep_w_k(
    const float* __restrict__ Wq, const float* __restrict__ Wg,
    const float* __restrict__ Wo,
    __half* __restrict__ tq, __half* __restrict__ tg, __half* __restrict__ to_)
{
    __shared__ float sm[32][33];
    int t = blockIdx.x;
    const float* W;
    __half* dst;
    int N, tk, tn;
    if (t < 192)      { W = Wq; dst = tq; N = 768; tk = t / 24; tn = t % 24; }
    else if (t < 256) { int u = t - 192; W = Wg; dst = tg; N = 256; tk = u / 8; tn = u % 8; }
    else              { int u = t - 256; W = Wo; dst = to_; N = 256; tk = u / 8; tn = u % 8; }
    const int tx = threadIdx.x & 31, ty = threadIdx.x >> 5;
    const int k0 = tk * 32, n0 = tn * 32;
#pragma unroll
    for (int i = 0; i < 4; i++)
        sm[ty + i * 8][tx] = W[(size_t)(k0 + ty + i * 8) * N + n0 + tx];
    __syncthreads();
#pragma unroll
    for (int i = 0; i < 4; i++)
        dst[(size_t)(n0 + ty + i * 8) * 256 + k0 + tx] = __float2half(sm[tx][ty + i * 8]);
}

// ============================================================================
// Tensor-core GEMM (wmma fp16, fp32 accum).
// TERMS=2: D = Ah*B + Al*B ; TERMS=1: D = Ah*B.
// MODE 0 additionally drops the Al term for v column-blocks (n0 >= 512).
// CTA = 128x128, 8 warps (4x2), warp tile 32x64, 2 CTAs/SM.
// ============================================================================
template <int MODE, int TERMS>
__global__ __launch_bounds__(256, 2) void tc_gemm(
    const __half* __restrict__ Ah, const __half* __restrict__ Al,
    const __half* __restrict__ Bh,
    float* __restrict__ Cp, int ldc,
    const float* __restrict__ bias, const float* __restrict__ attn,
    const float* __restrict__ ssq, const float* __restrict__ won,
    const float* __restrict__ wqn, const float* __restrict__ wkn,
    __half* __restrict__ qh_o, __half* __restrict__ ql_o, __half* __restrict__ kh_o,
    float* __restrict__ vf,
    __half* __restrict__ so_h)
{
    extern __shared__ char smem[];
    const int tid = threadIdx.x, wid = tid >> 5, lane = tid & 31;
    const int n0 = blockIdx.x * 128, m0 = blockIdx.y * 128;
    const int wm = wid & 3, wn = wid >> 2;
    const int NTILES = TERMS + 1;
    const bool use_low = (TERMS == 2) && !(MODE == 0 && n0 >= 512);

    __half* stg = (__half*)smem;

    wmma::fragment<wmma::accumulator, 16, 16, 16, float> acc[2][4];
#pragma unroll
    for (int mi = 0; mi < 2; mi++)
#pragma unroll
        for (int ni = 0; ni < 4; ni++) wmma::fill_fragment(acc[mi][ni], 0.f);

    for (int kc = 0; kc < 8; kc++) {
#pragma unroll
        for (int it = 0; it < 2 * NTILES; it++) {
            int idx = tid + it * 256;
            int which = idx >> 9, t = idx & 511;
            int row = t >> 2, c8 = (t & 3) << 3;
            const __half* gp;
            if (which == 0)                       gp = Ah + (size_t)(m0 + row) * 256 + kc * 32 + c8;
            else if (TERMS == 2 && which == 1)    gp = Al + (size_t)(m0 + row) * 256 + kc * 32 + c8;
            else                                  gp = Bh + (size_t)(n0 + row) * 256 + kc * 32 + c8;
            *(uint4*)&stg[which * TILE_H + row * ASTR + c8] = *(const uint4*)gp;
        }
        __syncthreads();

        const __half* Ash = stg;
        const __half* Asl = stg + TILE_H;
        const __half* Bsh = stg + (NTILES - 1) * TILE_H;

#pragma unroll
        for (int kk = 0; kk < 32; kk += 16) {
            wmma::fragment<wmma::matrix_b, 16, 16, 16, __half, wmma::col_major> bh[4];
#pragma unroll
            for (int ni = 0; ni < 4; ni++)
                wmma::load_matrix_sync(bh[ni], &Bsh[(wn * 64 + ni * 16) * ASTR + kk], ASTR);
#pragma unroll
            for (int mi = 0; mi < 2; mi++) {
                wmma::fragment<wmma::matrix_a, 16, 16, 16, __half, wmma::row_major> ah;
                wmma::load_matrix_sync(ah, &Ash[(wm * 32 + mi * 16) * ASTR + kk], ASTR);
#pragma unroll
                for (int ni = 0; ni < 4; ni++)
                    wmma::mma_sync(acc[mi][ni], ah, bh[ni], acc[mi][ni]);
                if (TERMS == 2 && use_low) {
                    wmma::fragment<wmma::matrix_a, 16, 16, 16, __half, wmma::row_major> al;
                    wmma::load_matrix_sync(al, &Asl[(wm * 32 + mi * 16) * ASTR + kk], ASTR);
#pragma unroll
                    for (int ni = 0; ni < 4; ni++)
                        wmma::mma_sync(acc[mi][ni], al, bh[ni], acc[mi][ni]);
                }
            }
        }
        __syncthreads();
    }

    float* Cs = (float*)smem;
    float* Cw = Cs + wid * 32 * CSTR;
#pragma unroll
    for (int mi = 0; mi < 2; mi++)
#pragma unroll
        for (int ni = 0; ni < 4; ni++)
            wmma::store_matrix_sync(&Cw[mi * 16 * CSTR + ni * 16],
                                    acc[mi][ni], CSTR, wmma::mem_row_major);
    __syncwarp();

    const int nb2 = n0 + wn * 64;

    if (MODE == 0) {
        if (nb2 < 512) {
            const bool isq = (nb2 < 256);
            const int h = (isq ? nb2 : nb2 - 256) >> 6;
            const float* wn_ = isq ? wqn : wkn;
            {
                float ss = 0.f;
                float* rp = Cw + lane * CSTR;
#pragma unroll
                for (int c = 0; c < 64; c++) {
                    float v = silu(rp[c]);
                    ss += v * v;
                }
                float rinv = rsqrtf(ss * (1.f / 64.f) + 1e-6f);
#pragma unroll
                for (int c = 0; c < 32; c++) {
                    float q1 = silu(rp[c]) * rinv * wn_[c];
                    float q2 = silu(rp[c + 32]) * rinv * wn_[c + 32];
                    float freq = expf(-9.210340371976184f * (float)c * (1.f / 32.f));
                    float ang = (float)h * freq;
                    float cs = cosf(ang), sn = sinf(ang);
                    rp[c] = q1 * cs - q2 * sn;
                    rp[c + 32] = q1 * sn + q2 * cs;
                }
            }
            __syncwarp();
            for (int i = lane; i < 2048; i += 32) {
                int r = i >> 6, c = i & 63;
                int m = m0 + wm * 32 + r;
                float v = Cw[r * CSTR + c];
                int o = m * 256 + h * 64 + c;
                if (isq) {
                    __half hh = __float2half(v);
                    qh_o[o] = hh;
                    ql_o[o] = __float2half(v - __half2float(hh));
                } else {
                    kh_o[o] = __float2half(v);
                }
            }
        } else {
            for (int i = lane; i < 2048; i += 32) {
                int r = i >> 6, c = i & 63;
                int m = m0 + wm * 32 + r;
                int n = nb2 - 512 + c;
                float s = silu(Cw[r * CSTR + c]);
                vf[m * 256 + n] = s;
                so_h[m * 256 + n] = __float2half(s);
            }
        }
    } else if (MODE == 1) {
        for (int i = lane; i < 2048; i += 32) {
            int r = i >> 6, c = i & 63;
            int m = m0 + wm * 32 + r;
            int n = nb2 + c;
            float v = Cw[r * CSTR + c];
            float g = sigm(silu(v + bias[n]));
            float vv = vf[(size_t)m * 256 + n];
            const float* sq = ssq + m * 4;
            float irms = rsqrtf((sq[0] + sq[1] + sq[2] + sq[3]) * (1.f / 256.f) + 1e-6f);
            float o = attn[(size_t)m * 256 + n] * irms * won[n];
            float merged = g * vv + (1.f - g) * o;
            so_h[m * 256 + n] = __float2half(merged);
        }
    } else {
        for (int i = lane; i < 2048; i += 32) {
            int r = i >> 6, c = i & 63;
            int m = m0 + wm * 32 + r;
            int n = nb2 + c;
            Cp[(size_t)m * ldc + n] = silu(Cw[r * CSTR + c]);
        }
    }
}

// ============================================================================
// Local attention via wmma (S = Q@K^T, masked softmax, O = A@V).
// A weights single fp16 (AV 1-term). Emits ssq per (row,head).
// Block = (8x8 tile, head, batch), 256 threads, 2 CTAs/SM.
// ============================================================================
__global__ __launch_bounds__(256, 2) void attn_k(
    const __half* __restrict__ gqh, const __half* __restrict__ gql,
    const __half* __restrict__ gkh, const __half* __restrict__ gvh,
    const float* __restrict__ width, const float* __restrict__ sharp,
    float* __restrict__ out, float* __restrict__ ssq)
{
    extern __shared__ char smem[];
    __half* Vh = (__half*)(smem + VH_B);   // [208][72]
    __half* Kh = (__half*)(smem + KH_B);   // [208][72]
    __half* Qh = (__half*)(smem + QH_B);   // [64][72]
    __half* Ql = (__half*)(smem + QL_B);   // [64][72]
    float*  S  = (float*)(smem + S_B);     // [64][216]

    const int tile = blockIdx.x, h = blockIdx.y, b = blockIdx.z;
    const int ty0 = (tile >> 3) << 3;
    const int tx0 = (tile & 7) << 3;
    const int tid = threadIdx.x, wid = tid >> 5;

    const uint4 zero4 = make_uint4(0, 0, 0, 0);
    for (int idx = tid; idx < 4352; idx += 256) {
        int job = idx >> 3, c = (idx & 7) << 3;
        uint4 val = zero4;
        __half* dst;
        if (job < 416) {
            int isv = job >= 208;
            int sp = isv ? job - 208 : job;
            dst = (isv ? Vh : Kh) + sp * 72 + c;
            if (sp < 196) {
                int yy = ty0 - 3 + sp / 14;
                int xx = tx0 - 3 + sp % 14;
                if (yy >= 0 && yy < GRIDW && xx >= 0 && xx < GRIDW) {
                    int r = (b * GRIDW + yy) * GRIDW + xx;
                    val = *(const uint4*)&(isv ? gvh : gkh)[(size_t)r * 256 + h * 64 + c];
                }
            }
        } else {
            int r0 = job - 416;
            int isl = r0 >= 64;
            int p = r0 & 63;
            dst = (isl ? Ql : Qh) + p * 72 + c;
            int r = (b * GRIDW + ty0 + (p >> 3)) * GRIDW + tx0 + (p & 7);
            val = *(const uint4*)&(isl ? gql : gqh)[(size_t)r * 256 + h * 64 + c];
        }
        *(uint4*)dst = val;
    }
    __syncthreads();

    const int wm = wid & 3, wn = wid >> 2;

    // ---- QK MMA ----
    {
        const int JN0 = wn * 7, NJ = wn ? 6 : 7;
        wmma::fragment<wmma::accumulator, 16, 16, 16, float> sacc[7];
#pragma unroll
        for (int j = 0; j < 7; j++) wmma::fill_fragment(sacc[j], 0.f);
#pragma unroll
        for (int kt = 0; kt < 4; kt++) {
            wmma::fragment<wmma::matrix_a, 16, 16, 16, __half, wmma::row_major> aqh, aql;
            wmma::load_matrix_sync(aqh, &Qh[wm * 16 * 72 + kt * 16], 72);
            wmma::load_matrix_sync(aql, &Ql[wm * 16 * 72 + kt * 16], 72);
            for (int j = 0; j < NJ; j++) {
                wmma::fragment<wmma::matrix_b, 16, 16, 16, __half, wmma::col_major> bk;
                wmma::load_matrix_sync(bk, &Kh[(JN0 + j) * 16 * 72 + kt * 16], 72);
                wmma::mma_sync(sacc[j], aqh, bk, sacc[j]);
                wmma::mma_sync(sacc[j], aql, bk, sacc[j]);
            }
        }
        __syncthreads();
        for (int j = 0; j < NJ; j++)
            wmma::store_matrix_sync(&S[wm * 16 * 216 + (JN0 + j) * 16], sacc[j], 216,
                                    wmma::mem_row_major);
    }
    __syncthreads();

    // ---- softmax + A fp16 (in-place over S rows) ----
    {
        const int p = tid >> 2, sub = tid & 3;
        const int py = p >> 3, px = p & 7;
        const int row = (b * GRIDW + ty0 + py) * GRIDW + tx0 + px;
        const float wd = width[row * 4 + h];
        const float sh = sharp[row * 4 + h];
        float* srow = S + p * 216;

        float sr[13];
#pragma unroll
        for (int j = 0; j < 13; j++) {
            int w = sub + 4 * j;
            if (w < 49) {
                int wy = w / 7, wx = w % 7;
                float dy = (float)(wy - 3), dx = (float)(wx - 3);
                float rd = sqrtf(dy * dy + dx * dx);
                float soft = sigm((wd - rd) * sh);
                sr[j] = srow[(py + wy) * 14 + px + wx] * 0.125f - (1.f - soft) * 10000.f;
            } else {
                sr[j] = -1e30f;
            }
        }
        float mx = sr[0];
#pragma unroll
        for (int j = 1; j < 13; j++) mx = fmaxf(mx, sr[j]);
        mx = fmaxf(mx, __shfl_xor_sync(0xffffffffu, mx, 1));
        mx = fmaxf(mx, __shfl_xor_sync(0xffffffffu, mx, 2));
        float sum = 0.f;
#pragma unroll
        for (int j = 0; j < 13; j++) {
            float e = expf(sr[j] - mx);
            sr[j] = e;
            sum += e;
        }
        sum += __shfl_xor_sync(0xffffffffu, sum, 1);
        sum += __shfl_xor_sync(0xffffffffu, sum, 2);
        float inv = 1.f / sum;

        __syncwarp();
        // zero-fill A region: 224 halves (>=208) per row, 56 float2 / 4 subs
        float2* zrow = (float2*)srow;
#pragma unroll
        for (int i = 0; i < 14; i++) zrow[sub * 14 + i] = make_float2(0.f, 0.f);
        __syncwarp();
        __half* ah_row = (__half*)srow;
#pragma unroll
        for (int j = 0; j < 13; j++) {
            int w = sub + 4 * j;
            if (w < 49) {
                int hi = (py + w / 7) * 14 + px + w % 7;
                ah_row[hi] = __float2half(sr[j] * inv);
            }
        }
    }
    __syncthreads();

    // ---- AV MMA (1-term) ----
    {
        const __half* Ahp = (const __half*)(smem + S_B);    // row stride 432 halves
        wmma::fragment<wmma::accumulator, 16, 16, 16, float> oacc[2];
        wmma::fill_fragment(oacc[0], 0.f);
        wmma::fill_fragment(oacc[1], 0.f);
        for (int kt = 0; kt < 13; kt++) {
            wmma::fragment<wmma::matrix_a, 16, 16, 16, __half, wmma::row_major> fah;
            wmma::load_matrix_sync(fah, &Ahp[wm * 16 * 432 + kt * 16], 432);
#pragma unroll
            for (int ni = 0; ni < 2; ni++) {
                wmma::fragment<wmma::matrix_b, 16, 16, 16, __half, wmma::row_major> bv;
                wmma::load_matrix_sync(bv, &Vh[kt * 16 * 72 + wn * 32 + ni * 16], 72);
                wmma::mma_sync(oacc[ni], fah, bv, oacc[ni]);
            }
        }
        __syncthreads();
        float* O = (float*)(smem + S_B);
#pragma unroll
        for (int ni = 0; ni < 2; ni++)
            wmma::store_matrix_sync(&O[wm * 16 * 72 + wn * 32 + ni * 16], oacc[ni], 72,
                                    wmma::mem_row_major);
    }
    __syncthreads();

    // ---- write out + per-position sum-of-squares ----
    {
        const float* O = (const float*)(smem + S_B);
        for (int idx = tid; idx < 1024; idx += 256) {
            int p = idx >> 4, d4 = (idx & 15) << 2;
            int r = (b * GRIDW + ty0 + (p >> 3)) * GRIDW + tx0 + (p & 7);
            *(float4*)&out[(size_t)r * 256 + h * 64 + d4] = *(const float4*)&O[p * 72 + d4];
        }
        int p = tid >> 2, qd = tid & 3;
        float s = 0.f;
#pragma unroll
        for (int i = 0; i < 16; i++) {
            float v = O[p * 72 + qd * 16 + i];
            s += v * v;
        }
        s += __shfl_xor_sync(0xffffffffu, s, 1);
        s += __shfl_xor_sync(0xffffffffu, s, 2);
        if (qd == 0) {
            int r = (b * GRIDW + ty0 + (p >> 3)) * GRIDW + tx0 + (p & 7);
            ssq[r * 4 + h] = s;
        }
    }
}

// ============================================================================
extern "C" void kernel_launch(void* const* d_in, const int* in_sizes, int n_in,
                              void* d_out, int out_size)
{
    const float* x      = (const float*)d_in[0];
    const float* W_qkv  = (const float*)d_in[1];
    const float* w_qn   = (const float*)d_in[2];
    const float* w_kn   = (const float*)d_in[3];
    const float* W_wp   = (const float*)d_in[4];
    const float* b_wp   = (const float*)d_in[5];
    const float* w_on   = (const float*)d_in[6];
    const float* W_out  = (const float*)d_in[7];
    const float* W_gate = (const float*)d_in[8];
    const float* b_gate = (const float*)d_in[9];
    float* out = (float*)d_out;

    float *vf, *wd, *sh, *attn, *ssq;
    __half *xh, *xl, *qh, *ql, *kh, *vh, *mh, *wq, *wg, *wo;
    cudaGetSymbolAddress((void**)&vf, g_vf);
    cudaGetSymbolAddress((void**)&wd, g_width);
    cudaGetSymbolAddress((void**)&sh, g_sharp);
    cudaGetSymbolAddress((void**)&attn, g_attn);
    cudaGetSymbolAddress((void**)&ssq, g_ssq);
    cudaGetSymbolAddress((void**)&xh, g_xh);
    cudaGetSymbolAddress((void**)&xl, g_xl);
    cudaGetSymbolAddress((void**)&qh, g_qh);
    cudaGetSymbolAddress((void**)&ql, g_ql);
    cudaGetSymbolAddress((void**)&kh, g_kh);
    cudaGetSymbolAddress((void**)&vh, g_vh);
    cudaGetSymbolAddress((void**)&mh, g_mh);
    cudaGetSymbolAddress((void**)&wq, g_wq);
    cudaGetSymbolAddress((void**)&wg, g_wg);
    cudaGetSymbolAddress((void**)&wo, g_wo);

    cudaFuncSetAttribute(attn_k, cudaFuncAttributeMaxDynamicSharedMemorySize, SMEM_AT);
    const int SMEM_TC = 8 * 32 * CSTR * 4;   // 69,632 B
    cudaFuncSetAttribute(tc_gemm<0, 2>, cudaFuncAttributeMaxDynamicSharedMemorySize, SMEM_TC);
    cudaFuncSetAttribute(tc_gemm<1, 1>, cudaFuncAttributeMaxDynamicSharedMemorySize, SMEM_TC);
    cudaFuncSetAttribute(tc_gemm<2, 1>, cudaFuncAttributeMaxDynamicSharedMemorySize, SMEM_TC);

    // 0) operand prep
    prep_x_k<<<NROWS / 8, 256>>>(x, W_wp, b_wp, xh, xl, wd, sh);
    prep_w_k<<<320, 256>>>(W_qkv, W_gate, W_out, wq, wg, wo);

    // 1) qkv GEMM (2-term q/k, 1-term v) + fused silu/rmsnorm/rope
    tc_gemm<0, 2><<<dim3(6, 64), 256, SMEM_TC>>>(xh, xl, wq, nullptr, 0,
                                                 nullptr, nullptr, nullptr, nullptr,
                                                 w_qn, w_kn, qh, ql, kh, vf, vh);
    // 2) local attention (tensor cores) + ssq
    attn_k<<<dim3(64, HEADS, 2), 256, SMEM_AT>>>(qh, ql, kh, vh, wd, sh, attn, ssq);
    // 3) gate GEMM (1-term) + merge epilogue (irms from ssq) -> mh
    tc_gemm<1, 1><<<dim3(2, 64), 256, SMEM_TC>>>(vh, nullptr, wg, nullptr, 0,
                                                 b_gate, attn, ssq, w_on,
                                                 nullptr, nullptr,
                                                 nullptr, nullptr, nullptr, vf, mh);
    // 4) out = silu(merged @ W_out)  (1-term)
    tc_gemm<2, 1><<<dim3(2, 64), 256, SMEM_TC>>>(mh, nullptr, wo, out, 256,
                                                 nullptr, nullptr, nullptr, nullptr,
                                                 nullptr, nullptr,
                                                 nullptr, nullptr, nullptr, nullptr,
                                                 nullptr);
}

// round 17
// speedup vs baseline: 2.1836x; 1.4049x over previous
#include <cuda_runtime.h>
#include <cuda_fp16.h>
#include <mma.h>
#include <math.h>
#include <stdint.h>

using namespace nvcuda;

#define NROWS 8192   // B*Hs*Ws = 2*64*64
#define CDIM  256
#define HEADS 4
#define HD    64
#define GRIDW 64     // Hs = Ws
#define ASTR  40     // gemm staging smem stride (halves) -> 80B rows
#define CSTR  68     // gemm epilogue smem stride (fp32)
#define TILE_H (128 * ASTR)

// attn smem layout (bytes)
#define VH_B   0          // Vh fp16 [208][72]
#define KH_B   29952      // Kh fp16 [208][72]   (inside S region, freed before S store)
#define QH_B   59904      // Qh fp16 [64][72]    (inside S region, freed before S store)
#define S_B    29952      // S fp32 [64][216]  (A fp16 in-place; O fp32 after)
#define SMEM_AT 85248

// -------- scratch (no allocations allowed) --------
__device__ __align__(256) float g_vf[NROWS * CDIM];
__device__ __align__(256) float g_width[NROWS * HEADS];
__device__ __align__(256) float g_sharp[NROWS * HEADS];
__device__ __align__(256) float g_attn[NROWS * CDIM];
__device__ __align__(256) float g_ssq[NROWS * HEADS];
// fp16 operands
__device__ __align__(256) __half g_xh[NROWS * 256];
__device__ __align__(256) __half g_xl[NROWS * 256];
__device__ __align__(256) __half g_qh[NROWS * 256];
__device__ __align__(256) __half g_kh[NROWS * 256];
__device__ __align__(256) __half g_vh[NROWS * 256];
__device__ __align__(256) __half g_mh[NROWS * 256];
// weights transposed to [N][K] fp16
__device__ __align__(256) __half g_wq[768 * 256];
__device__ __align__(256) __half g_wg[256 * 256];
__device__ __align__(256) __half g_wo[256 * 256];

// window distance + halo-offset tables (dy,dx in -3..3)
__device__ __constant__ float RD49[49] = {
    4.2426406871f, 3.6055512755f, 3.1622776602f, 3.0f, 3.1622776602f, 3.6055512755f, 4.2426406871f,
    3.6055512755f, 2.8284271247f, 2.2360679775f, 2.0f, 2.2360679775f, 2.8284271247f, 3.6055512755f,
    3.1622776602f, 2.2360679775f, 1.4142135624f, 1.0f, 1.4142135624f, 2.2360679775f, 3.1622776602f,
    3.0f, 2.0f, 1.0f, 0.0f, 1.0f, 2.0f, 3.0f,
    3.1622776602f, 2.2360679775f, 1.4142135624f, 1.0f, 1.4142135624f, 2.2360679775f, 3.1622776602f,
    3.6055512755f, 2.8284271247f, 2.2360679775f, 2.0f, 2.2360679775f, 2.8284271247f, 3.6055512755f,
    4.2426406871f, 3.6055512755f, 3.1622776602f, 3.0f, 3.1622776602f, 3.6055512755f, 4.2426406871f };
__device__ __constant__ int OFF49[49] = {
     0,  1,  2,  3,  4,  5,  6,
    14, 15, 16, 17, 18, 19, 20,
    28, 29, 30, 31, 32, 33, 34,
    42, 43, 44, 45, 46, 47, 48,
    56, 57, 58, 59, 60, 61, 62,
    70, 71, 72, 73, 74, 75, 76,
    84, 85, 86, 87, 88, 89, 90 };

__device__ __forceinline__ float sigm(float x) { return __fdividef(1.f, 1.f + __expf(-x)); }
__device__ __forceinline__ float silu(float x) { return __fdividef(x, 1.f + __expf(-x)); }

// ============================================================================
// prep 1: per-row — fp16 split of x AND width/sharpness projection (warp/row)
// ============================================================================
__global__ __launch_bounds__(256) void prep_x_k(
    const float* __restrict__ x, const float* __restrict__ W,
    const float* __restrict__ bias,
    __half* __restrict__ xh, __half* __restrict__ xl,
    float* __restrict__ width, float* __restrict__ sharp)
{
    int row = (blockIdx.x * 256 + threadIdx.x) >> 5;
    int lane = threadIdx.x & 31;
    if (row >= NROWS) return;
    const float* xr = x + (size_t)row * 256;
    float acc[8] = {0, 0, 0, 0, 0, 0, 0, 0};
#pragma unroll
    for (int i = 0; i < 8; i++) {
        int k = lane + 32 * i;
        float v = xr[k];
        __half h = __float2half(v);
        xh[row * 256 + k] = h;
        xl[row * 256 + k] = __float2half(v - __half2float(h));
#pragma unroll
        for (int j = 0; j < 8; j++) acc[j] += v * W[k * 8 + j];
    }
#pragma unroll
    for (int off = 16; off; off >>= 1)
#pragma unroll
        for (int j = 0; j < 8; j++) acc[j] += __shfl_xor_sync(0xffffffffu, acc[j], off);
    if (lane == 0) {
#pragma unroll
        for (int j = 0; j < 4; j++) {
            float wr = silu(acc[j] + bias[j]);
            width[row * 4 + j] = sigm(wr) * 4.2426406871192851f + 0.5f;
            float sr = silu(acc[4 + j] + bias[4 + j]);
            sharp[row * 4 + j] = sigm(sr) * 9.5f + 0.5f;
        }
    }
}

// ============================================================================
// prep 2: weights: W [K,N] fp32 -> Wt [N,K] fp16, 32x32 smem-tiled transpose.
// ============================================================================
__global__ __launch_bounds__(256) void prep_w_k(
    const float* __restrict__ Wq, const float* __restrict__ Wg,
    const float* __restrict__ Wo,
    __half* __restrict__ tq, __half* __restrict__ tg, __half* __restrict__ to_)
{
    __shared__ float sm[32][33];
    int t = blockIdx.x;
    const float* W;
    __half* dst;
    int N, tk, tn;
    if (t < 192)      { W = Wq; dst = tq; N = 768; tk = t / 24; tn = t % 24; }
    else if (t < 256) { int u = t - 192; W = Wg; dst = tg; N = 256; tk = u / 8; tn = u % 8; }
    else              { int u = t - 256; W = Wo; dst = to_; N = 256; tk = u / 8; tn = u % 8; }
    const int tx = threadIdx.x & 31, ty = threadIdx.x >> 5;
    const int k0 = tk * 32, n0 = tn * 32;
#pragma unroll
    for (int i = 0; i < 4; i++)
        sm[ty + i * 8][tx] = W[(size_t)(k0 + ty + i * 8) * N + n0 + tx];
    __syncthreads();
#pragma unroll
    for (int i = 0; i < 4; i++)
        dst[(size_t)(n0 + ty + i * 8) * 256 + k0 + tx] = __float2half(sm[tx][ty + i * 8]);
}

// ============================================================================
// Tensor-core GEMM (wmma fp16, fp32 accum).
// TERMS=2: D = Ah*B + Al*B ; TERMS=1: D = Ah*B.
// MODE 0 additionally drops the Al term for v column-blocks (n0 >= 512).
// CTA = 128x128, 8 warps (4x2), warp tile 32x64, 2 CTAs/SM.
// ============================================================================
template <int MODE, int TERMS>
__global__ __launch_bounds__(256, 2) void tc_gemm(
    const __half* __restrict__ Ah, const __half* __restrict__ Al,
    const __half* __restrict__ Bh,
    float* __restrict__ Cp, int ldc,
    const float* __restrict__ bias, const float* __restrict__ attn,
    const float* __restrict__ ssq, const float* __restrict__ won,
    const float* __restrict__ wqn, const float* __restrict__ wkn,
    __half* __restrict__ qh_o, __half* __restrict__ kh_o,
    float* __restrict__ vf,
    __half* __restrict__ so_h)
{
    extern __shared__ char smem[];
    const int tid = threadIdx.x, wid = tid >> 5, lane = tid & 31;
    const int n0 = blockIdx.x * 128, m0 = blockIdx.y * 128;
    const int wm = wid & 3, wn = wid >> 2;
    const int NTILES = TERMS + 1;
    const bool use_low = (TERMS == 2) && !(MODE == 0 && n0 >= 512);

    __half* stg = (__half*)smem;

    wmma::fragment<wmma::accumulator, 16, 16, 16, float> acc[2][4];
#pragma unroll
    for (int mi = 0; mi < 2; mi++)
#pragma unroll
        for (int ni = 0; ni < 4; ni++) wmma::fill_fragment(acc[mi][ni], 0.f);

    for (int kc = 0; kc < 8; kc++) {
#pragma unroll
        for (int it = 0; it < 2 * NTILES; it++) {
            int idx = tid + it * 256;
            int which = idx >> 9, t = idx & 511;
            int row = t >> 2, c8 = (t & 3) << 3;
            const __half* gp;
            if (which == 0)                       gp = Ah + (size_t)(m0 + row) * 256 + kc * 32 + c8;
            else if (TERMS == 2 && which == 1)    gp = Al + (size_t)(m0 + row) * 256 + kc * 32 + c8;
            else                                  gp = Bh + (size_t)(n0 + row) * 256 + kc * 32 + c8;
            *(uint4*)&stg[which * TILE_H + row * ASTR + c8] = *(const uint4*)gp;
        }
        __syncthreads();

        const __half* Ash = stg;
        const __half* Asl = stg + TILE_H;
        const __half* Bsh = stg + (NTILES - 1) * TILE_H;

#pragma unroll
        for (int kk = 0; kk < 32; kk += 16) {
            wmma::fragment<wmma::matrix_b, 16, 16, 16, __half, wmma::col_major> bh[4];
#pragma unroll
            for (int ni = 0; ni < 4; ni++)
                wmma::load_matrix_sync(bh[ni], &Bsh[(wn * 64 + ni * 16) * ASTR + kk], ASTR);
#pragma unroll
            for (int mi = 0; mi < 2; mi++) {
                wmma::fragment<wmma::matrix_a, 16, 16, 16, __half, wmma::row_major> ah;
                wmma::load_matrix_sync(ah, &Ash[(wm * 32 + mi * 16) * ASTR + kk], ASTR);
#pragma unroll
                for (int ni = 0; ni < 4; ni++)
                    wmma::mma_sync(acc[mi][ni], ah, bh[ni], acc[mi][ni]);
                if (TERMS == 2 && use_low) {
                    wmma::fragment<wmma::matrix_a, 16, 16, 16, __half, wmma::row_major> al;
                    wmma::load_matrix_sync(al, &Asl[(wm * 32 + mi * 16) * ASTR + kk], ASTR);
#pragma unroll
                    for (int ni = 0; ni < 4; ni++)
                        wmma::mma_sync(acc[mi][ni], al, bh[ni], acc[mi][ni]);
                }
            }
        }
        __syncthreads();
    }

    float* Cs = (float*)smem;
    float* Cw = Cs + wid * 32 * CSTR;
#pragma unroll
    for (int mi = 0; mi < 2; mi++)
#pragma unroll
        for (int ni = 0; ni < 4; ni++)
            wmma::store_matrix_sync(&Cw[mi * 16 * CSTR + ni * 16],
                                    acc[mi][ni], CSTR, wmma::mem_row_major);
    __syncwarp();

    const int nb2 = n0 + wn * 64;

    if (MODE == 0) {
        if (nb2 < 512) {
            const bool isq = (nb2 < 256);
            const int h = (isq ? nb2 : nb2 - 256) >> 6;
            const float* wn_ = isq ? wqn : wkn;
            {
                float ss = 0.f;
                float* rp = Cw + lane * CSTR;
#pragma unroll
                for (int c = 0; c < 64; c++) {
                    float v = silu(rp[c]);
                    ss += v * v;
                }
                float rinv = rsqrtf(ss * (1.f / 64.f) + 1e-6f);
#pragma unroll
                for (int c = 0; c < 32; c++) {
                    float q1 = silu(rp[c]) * rinv * wn_[c];
                    float q2 = silu(rp[c + 32]) * rinv * wn_[c + 32];
                    float freq = __expf(-9.210340371976184f * (float)c * (1.f / 32.f));
                    float ang = (float)h * freq;
                    float cs, sn;
                    __sincosf(ang, &sn, &cs);
                    rp[c] = q1 * cs - q2 * sn;
                    rp[c + 32] = q1 * sn + q2 * cs;
                }
            }
            __syncwarp();
            __half* dst = isq ? qh_o : kh_o;
            for (int i = lane; i < 2048; i += 32) {
                int r = i >> 6, c = i & 63;
                int m = m0 + wm * 32 + r;
                dst[m * 256 + h * 64 + c] = __float2half(Cw[r * CSTR + c]);
            }
        } else {
            for (int i = lane; i < 2048; i += 32) {
                int r = i >> 6, c = i & 63;
                int m = m0 + wm * 32 + r;
                int n = nb2 - 512 + c;
                float s = silu(Cw[r * CSTR + c]);
                vf[m * 256 + n] = s;
                so_h[m * 256 + n] = __float2half(s);
            }
        }
    } else if (MODE == 1) {
        for (int i = lane; i < 2048; i += 32) {
            int r = i >> 6, c = i & 63;
            int m = m0 + wm * 32 + r;
            int n = nb2 + c;
            float v = Cw[r * CSTR + c];
            float g = sigm(silu(v + bias[n]));
            float vv = vf[(size_t)m * 256 + n];
            const float* sq = ssq + m * 4;
            float irms = rsqrtf((sq[0] + sq[1] + sq[2] + sq[3]) * (1.f / 256.f) + 1e-6f);
            float o = attn[(size_t)m * 256 + n] * irms * won[n];
            float merged = g * vv + (1.f - g) * o;
            so_h[m * 256 + n] = __float2half(merged);
        }
    } else {
        for (int i = lane; i < 2048; i += 32) {
            int r = i >> 6, c = i & 63;
            int m = m0 + wm * 32 + r;
            int n = nb2 + c;
            Cp[(size_t)m * ldc + n] = silu(Cw[r * CSTR + c]);
        }
    }
}

// ============================================================================
// Local attention via wmma. q,k,A all single fp16 (QK 1-term, AV 1-term).
// Fast softmax: const RD/OFF tables, __expf. Emits ssq per (row,head).
// Block = (8x8 tile, head, batch), 256 threads, 2 CTAs/SM.
// ============================================================================
__global__ __launch_bounds__(256, 2) void attn_k(
    const __half* __restrict__ gqh, const __half* __restrict__ gkh,
    const __half* __restrict__ gvh,
    const float* __restrict__ width, const float* __restrict__ sharp,
    float* __restrict__ out, float* __restrict__ ssq)
{
    extern __shared__ char smem[];
    __half* Vh = (__half*)(smem + VH_B);   // [208][72]
    __half* Kh = (__half*)(smem + KH_B);   // [208][72]
    __half* Qh = (__half*)(smem + QH_B);   // [64][72]
    float*  S  = (float*)(smem + S_B);     // [64][216]

    const int tile = blockIdx.x, h = blockIdx.y, b = blockIdx.z;
    const int ty0 = (tile >> 3) << 3;
    const int tx0 = (tile & 7) << 3;
    const int tid = threadIdx.x, wid = tid >> 5;

    const uint4 zero4 = make_uint4(0, 0, 0, 0);
    for (int idx = tid; idx < 3840; idx += 256) {
        int job = idx >> 3, c = (idx & 7) << 3;
        uint4 val = zero4;
        __half* dst;
        if (job < 416) {
            int isv = job >= 208;
            int sp = isv ? job - 208 : job;
            dst = (isv ? Vh : Kh) + sp * 72 + c;
            if (sp < 196) {
                int yy = ty0 - 3 + sp / 14;
                int xx = tx0 - 3 + sp % 14;
                if (yy >= 0 && yy < GRIDW && xx >= 0 && xx < GRIDW) {
                    int r = (b * GRIDW + yy) * GRIDW + xx;
                    val = *(const uint4*)&(isv ? gvh : gkh)[(size_t)r * 256 + h * 64 + c];
                }
            }
        } else {
            int p = job - 416;
            dst = Qh + p * 72 + c;
            int r = (b * GRIDW + ty0 + (p >> 3)) * GRIDW + tx0 + (p & 7);
            val = *(const uint4*)&gqh[(size_t)r * 256 + h * 64 + c];
        }
        *(uint4*)dst = val;
    }
    __syncthreads();

    const int wm = wid & 3, wn = wid >> 2;

    // ---- QK MMA (1-term) ----
    {
        const int JN0 = wn * 7, NJ = wn ? 6 : 7;
        wmma::fragment<wmma::accumulator, 16, 16, 16, float> sacc[7];
#pragma unroll
        for (int j = 0; j < 7; j++) wmma::fill_fragment(sacc[j], 0.f);
#pragma unroll
        for (int kt = 0; kt < 4; kt++) {
            wmma::fragment<wmma::matrix_a, 16, 16, 16, __half, wmma::row_major> aqh;
            wmma::load_matrix_sync(aqh, &Qh[wm * 16 * 72 + kt * 16], 72);
            for (int j = 0; j < NJ; j++) {
                wmma::fragment<wmma::matrix_b, 16, 16, 16, __half, wmma::col_major> bk;
                wmma::load_matrix_sync(bk, &Kh[(JN0 + j) * 16 * 72 + kt * 16], 72);
                wmma::mma_sync(sacc[j], aqh, bk, sacc[j]);
            }
        }
        __syncthreads();   // all Q/K reads done before S overwrites Kh/Qh
        for (int j = 0; j < NJ; j++)
            wmma::store_matrix_sync(&S[wm * 16 * 216 + (JN0 + j) * 16], sacc[j], 216,
                                    wmma::mem_row_major);
    }
    __syncthreads();

    // ---- softmax + A fp16 (in-place over S rows) ----
    {
        const int p = tid >> 2, sub = tid & 3;
        const int py = p >> 3, px = p & 7;
        const int row = (b * GRIDW + ty0 + py) * GRIDW + tx0 + px;
        const float wd = width[row * 4 + h];
        const float sh = sharp[row * 4 + h];
        float* srow = S + p * 216;
        const int pbase = py * 14 + px;

        float sr[13];
#pragma unroll
        for (int j = 0; j < 13; j++) {
            int w = sub + 4 * j;
            if (w < 49) {
                float soft = sigm((wd - RD49[w]) * sh);
                sr[j] = srow[pbase + OFF49[w]] * 0.125f - (1.f - soft) * 10000.f;
            } else {
                sr[j] = -1e30f;
            }
        }
        float mx = sr[0];
#pragma unroll
        for (int j = 1; j < 13; j++) mx = fmaxf(mx, sr[j]);
        mx = fmaxf(mx, __shfl_xor_sync(0xffffffffu, mx, 1));
        mx = fmaxf(mx, __shfl_xor_sync(0xffffffffu, mx, 2));
        float sum = 0.f;
#pragma unroll
        for (int j = 0; j < 13; j++) {
            float e = __expf(sr[j] - mx);
            sr[j] = e;
            sum += e;
        }
        sum += __shfl_xor_sync(0xffffffffu, sum, 1);
        sum += __shfl_xor_sync(0xffffffffu, sum, 2);
        float inv = __fdividef(1.f, sum);

        __syncwarp();
        float2* zrow = (float2*)srow;
#pragma unroll
        for (int i = 0; i < 14; i++) zrow[sub * 14 + i] = make_float2(0.f, 0.f);
        __syncwarp();
        __half* ah_row = (__half*)srow;
#pragma unroll
        for (int j = 0; j < 13; j++) {
            int w = sub + 4 * j;
            if (w < 49)
                ah_row[pbase + OFF49[w]] = __float2half(sr[j] * inv);
        }
    }
    __syncthreads();

    // ---- AV MMA (1-term) ----
    {
        const __half* Ahp = (const __half*)(smem + S_B);    // row stride 432 halves
        wmma::fragment<wmma::accumulator, 16, 16, 16, float> oacc[2];
        wmma::fill_fragment(oacc[0], 0.f);
        wmma::fill_fragment(oacc[1], 0.f);
        for (int kt = 0; kt < 13; kt++) {
            wmma::fragment<wmma::matrix_a, 16, 16, 16, __half, wmma::row_major> fah;
            wmma::load_matrix_sync(fah, &Ahp[wm * 16 * 432 + kt * 16], 432);
#pragma unroll
            for (int ni = 0; ni < 2; ni++) {
                wmma::fragment<wmma::matrix_b, 16, 16, 16, __half, wmma::row_major> bv;
                wmma::load_matrix_sync(bv, &Vh[kt * 16 * 72 + wn * 32 + ni * 16], 72);
                wmma::mma_sync(oacc[ni], fah, bv, oacc[ni]);
            }
        }
        __syncthreads();
        float* O = (float*)(smem + S_B);
#pragma unroll
        for (int ni = 0; ni < 2; ni++)
            wmma::store_matrix_sync(&O[wm * 16 * 72 + wn * 32 + ni * 16], oacc[ni], 72,
                                    wmma::mem_row_major);
    }
    __syncthreads();

    // ---- write out + per-position sum-of-squares ----
    {
        const float* O = (const float*)(smem + S_B);
        for (int idx = tid; idx < 1024; idx += 256) {
            int p = idx >> 4, d4 = (idx & 15) << 2;
            int r = (b * GRIDW + ty0 + (p >> 3)) * GRIDW + tx0 + (p & 7);
            *(float4*)&out[(size_t)r * 256 + h * 64 + d4] = *(const float4*)&O[p * 72 + d4];
        }
        int p = tid >> 2, qd = tid & 3;
        float s = 0.f;
#pragma unroll
        for (int i = 0; i < 16; i++) {
            float v = O[p * 72 + qd * 16 + i];
            s += v * v;
        }
        s += __shfl_xor_sync(0xffffffffu, s, 1);
        s += __shfl_xor_sync(0xffffffffu, s, 2);
        if (qd == 0) {
            int r = (b * GRIDW + ty0 + (p >> 3)) * GRIDW + tx0 + (p & 7);
            ssq[r * 4 + h] = s;
        }
    }
}

// ============================================================================
extern "C" void kernel_launch(void* const* d_in, const int* in_sizes, int n_in,
                              void* d_out, int out_size)
{
    const float* x      = (const float*)d_in[0];
    const float* W_qkv  = (const float*)d_in[1];
    const float* w_qn   = (const float*)d_in[2];
    const float* w_kn   = (const float*)d_in[3];
    const float* W_wp   = (const float*)d_in[4];
    const float* b_wp   = (const float*)d_in[5];
    const float* w_on   = (const float*)d_in[6];
    const float* W_out  = (const float*)d_in[7];
    const float* W_gate = (const float*)d_in[8];
    const float* b_gate = (const float*)d_in[9];
    float* out = (float*)d_out;

    float *vf, *wd, *sh, *attn, *ssq;
    __half *xh, *xl, *qh, *kh, *vh, *mh, *wq, *wg, *wo;
    cudaGetSymbolAddress((void**)&vf, g_vf);
    cudaGetSymbolAddress((void**)&wd, g_width);
    cudaGetSymbolAddress((void**)&sh, g_sharp);
    cudaGetSymbolAddress((void**)&attn, g_attn);
    cudaGetSymbolAddress((void**)&ssq, g_ssq);
    cudaGetSymbolAddress((void**)&xh, g_xh);
    cudaGetSymbolAddress((void**)&xl, g_xl);
    cudaGetSymbolAddress((void**)&qh, g_qh);
    cudaGetSymbolAddress((void**)&kh, g_kh);
    cudaGetSymbolAddress((void**)&vh, g_vh);
    cudaGetSymbolAddress((void**)&mh, g_mh);
    cudaGetSymbolAddress((void**)&wq, g_wq);
    cudaGetSymbolAddress((void**)&wg, g_wg);
    cudaGetSymbolAddress((void**)&wo, g_wo);

    cudaFuncSetAttribute(attn_k, cudaFuncAttributeMaxDynamicSharedMemorySize, SMEM_AT);
    const int SMEM_TC = 8 * 32 * CSTR * 4;   // 69,632 B
    cudaFuncSetAttribute(tc_gemm<0, 2>, cudaFuncAttributeMaxDynamicSharedMemorySize, SMEM_TC);
    cudaFuncSetAttribute(tc_gemm<1, 1>, cudaFuncAttributeMaxDynamicSharedMemorySize, SMEM_TC);
    cudaFuncSetAttribute(tc_gemm<2, 1>, cudaFuncAttributeMaxDynamicSharedMemorySize, SMEM_TC);

    // 0) operand prep
    prep_x_k<<<NROWS / 8, 256>>>(x, W_wp, b_wp, xh, xl, wd, sh);
    prep_w_k<<<320, 256>>>(W_qkv, W_gate, W_out, wq, wg, wo);

    // 1) qkv GEMM (2-term q/k, 1-term v) + fused silu/rmsnorm/rope
    tc_gemm<0, 2><<<dim3(6, 64), 256, SMEM_TC>>>(xh, xl, wq, nullptr, 0,
                                                 nullptr, nullptr, nullptr, nullptr,
                                                 w_qn, w_kn, qh, kh, vf, vh);
    // 2) local attention (tensor cores) + ssq
    attn_k<<<dim3(64, HEADS, 2), 256, SMEM_AT>>>(qh, kh, vh, wd, sh, attn, ssq);
    // 3) gate GEMM (1-term) + merge epilogue (irms from ssq) -> mh
    tc_gemm<1, 1><<<dim3(2, 64), 256, SMEM_TC>>>(vh, nullptr, wg, nullptr, 0,
                                                 b_gate, attn, ssq, w_on,
                                                 nullptr, nullptr,
                                                 nullptr, nullptr, vf, mh);
    // 4) out = silu(merged @ W_out)  (1-term)
    tc_gemm<2, 1><<<dim3(2, 64), 256, SMEM_TC>>>(mh, nullptr, wo, out, 256,
                                                 nullptr, nullptr, nullptr, nullptr,
                                                 nullptr, nullptr,
                                                 nullptr, nullptr, nullptr,
                                                 nullptr);
}